// round 14
// baseline (speedup 1.0000x reference)
#include <cuda_runtime.h>
#include <cuda_bf16.h>
#include <cstdint>

#define NB   2
#define NC   512
#define NN   4096
#define NUU  1024
#define NHEAD 8
#define HD   64
#define SCALE_ 0.125f

// ---------------- mma.sync helpers --------------------------------------------
__device__ __forceinline__ unsigned smem_u32(const void* p) {
    unsigned a;
    asm("{ .reg .u64 t; cvta.to.shared.u64 t, %1; cvt.u32.u64 %0, t; }" : "=r"(a) : "l"(p));
    return a;
}
#define SWZ(o) ((o) ^ (((o) >> 3) & 0x70))

#define LDMX4(r, addr) \
    asm volatile("ldmatrix.sync.aligned.m8n8.x4.shared.b16 {%0,%1,%2,%3},[%4];" \
        : "=r"((r)[0]), "=r"((r)[1]), "=r"((r)[2]), "=r"((r)[3]) : "r"(addr))

#define MMA16816(d, a, b0, b1) \
    asm volatile("mma.sync.aligned.m16n8k16.row.col.f32.bf16.bf16.f32 " \
        "{%0,%1,%2,%3},{%4,%5,%6,%7},{%8,%9},{%0,%1,%2,%3};" \
        : "+f"((d)[0]), "+f"((d)[1]), "+f"((d)[2]), "+f"((d)[3]) \
        : "r"((a)[0]), "r"((a)[1]), "r"((a)[2]), "r"((a)[3]), "r"(b0), "r"(b1))

#define CPA16(dst, src) \
    asm volatile("cp.async.cg.shared.global [%0],[%1],16;" :: "r"(dst), "l"(src))
#define CPA_COMMIT() asm volatile("cp.async.commit_group;" ::: "memory")
#define CPA_WAIT(n)  asm volatile("cp.async.wait_group %0;" :: "n"(n) : "memory")

__device__ __forceinline__ unsigned bfpack(__nv_bfloat16 a, __nv_bfloat16 b) {
    __nv_bfloat162 t(a, b); return *(unsigned*)&t;
}

// ---------------- scratch (device globals) ------------------------------------
__device__ float g_q     [NB*NHEAD*NN*HD];        // [b,h,n,d]
__device__ float g_fk    [NB*NHEAD*NN*HD];
__device__ float g_fv    [NB*NHEAD*NN*HD];
__device__ float g_k     [NB*NHEAD*NUU*HD];       // [b,h,m,d]
__device__ float g_v     [NB*NHEAD*NUU*HD];
__device__ float g_coarse[NB*NHEAD*NN*HD];
__device__ float g_xsum  [NB*NC*NN];              // x_out (+ v_pe) in [b,c,n]
__device__ float g_heat  [NB*NUU];
__device__ float g_qmean [NB*NHEAD*HD];
__device__ int   g_idxf  [NB*NHEAD*64];
// pre-split bf16 weights: rows 0..511 = q_w, 512..1535 = kv_w, 1536..2047 = proj_w
__device__ __nv_bfloat16 g_wh [2048*512], g_wl [2048*512];
// pre-split bf16 conv inputs (same [b][512][N] layout as fp32 source)
__device__ __nv_bfloat16 g_xh [NB*NC*NN],  g_xl [NB*NC*NN];
__device__ __nv_bfloat16 g_uh [NB*NC*NUU], g_ul [NB*NC*NUU];
__device__ __nv_bfloat16 g_sh [NB*NC*NN],  g_sl [NB*NC*NN];
// pre-split bf16 operands for flash (produced by conv epilogues)
__device__ __nv_bfloat16 g_qh [NB*NHEAD*NN*HD],  g_ql [NB*NHEAD*NN*HD];
__device__ __nv_bfloat16 g_kh [NB*NHEAD*NUU*HD], g_kl [NB*NHEAD*NUU*HD];
__device__ __nv_bfloat16 g_vth[NB*NHEAD*HD*NUU], g_vtl[NB*NHEAD*HD*NUU];

// ---------------- weight pre-split ---------------------------------------------
__global__ void split_weights(const float* __restrict__ qw, const float* __restrict__ kvw,
                              const float* __restrict__ pw)
{
    int r = blockIdx.x;
    const float* src = r < 512 ? qw + (size_t)r * 512
                     : r < 1536 ? kvw + (size_t)(r - 512) * 512
                                : pw + (size_t)(r - 1536) * 512;
    for (int c = threadIdx.x; c < 512; c += 256) {
        float v = src[c];
        __nv_bfloat16 h = __float2bfloat16(v);
        g_wh[(size_t)r * 512 + c] = h;
        g_wl[(size_t)r * 512 + c] = __float2bfloat16(v - __bfloat162float(h));
    }
}

// ---------------- fp32 -> bf16 hi/lo elementwise split --------------------------
// DST: 0 = g_xh/g_xl, 1 = g_uh/g_ul, 2 = g_sh/g_sl (selected in device code!)
template<int DST>
__global__ void split_f32(const float* __restrict__ srcArg, int n4)
{
    const float* src = (DST == 2) ? g_xsum : srcArg;
    __nv_bfloat16* dh = DST == 0 ? g_xh : DST == 1 ? g_uh : g_sh;
    __nv_bfloat16* dl = DST == 0 ? g_xl : DST == 1 ? g_ul : g_sl;
    int i = blockIdx.x * 256 + threadIdx.x;
    if (i >= n4) return;
    float4 v = ((const float4*)src)[i];
    __nv_bfloat16 h0 = __float2bfloat16(v.x), h1 = __float2bfloat16(v.y);
    __nv_bfloat16 h2 = __float2bfloat16(v.z), h3 = __float2bfloat16(v.w);
    __nv_bfloat162 hA(h0, h1), hB(h2, h3);
    __nv_bfloat162 lA(__float2bfloat16(v.x - __bfloat162float(h0)),
                      __float2bfloat16(v.y - __bfloat162float(h1)));
    __nv_bfloat162 lB(__float2bfloat16(v.z - __bfloat162float(h2)),
                      __float2bfloat16(v.w - __bfloat162float(h3)));
    ((__nv_bfloat162*)dh)[2 * i]     = hA;
    ((__nv_bfloat162*)dh)[2 * i + 1] = hB;
    ((__nv_bfloat162*)dl)[2 * i]     = lA;
    ((__nv_bfloat162*)dl)[2 * i + 1] = lB;
}

// ---------------- conv1x1 GEMM via mma.sync bf16-split -------------------------
// X buffers selected by MODE in device code (0,1: g_xh ; 3: g_uh ; 2: g_sh)
#define CONV_SMEM (66048 + 1024)

template<int MODE>
__global__ void __launch_bounds__(256, 2)
conv_mma(int wrow, const float* __restrict__ bias, float* __restrict__ out, int N)
{
    extern __shared__ char smraw[];
    unsigned sb = smem_u32(smraw);
    unsigned base = (sb + 1023) & ~1023u;
    char* S = smraw + (base - sb);
    const unsigned S_WH = 0, S_WL = 16384, S_XH = 32768, S_XL = 49152;
    float* Ds = (float*)S;
    __shared__ float sbias[128];

    int tid = threadIdx.x, l = tid & 31, wid = tid >> 5;
    int warp_o = wid & 3, warp_n = wid >> 2;
    int b = blockIdx.z, otile = blockIdx.y * 128, ntile = blockIdx.x * 128;
    const __nv_bfloat16* Xhb = (MODE == 3 ? g_uh : MODE == 2 ? g_sh : g_xh)
                               + (size_t)b * 512 * N;
    const __nv_bfloat16* Xlb = (MODE == 3 ? g_ul : MODE == 2 ? g_sl : g_xl)
                               + (size_t)b * 512 * N;
    const __nv_bfloat16* Wh = g_wh + (size_t)(wrow + otile) * 512;
    const __nv_bfloat16* Wl = g_wl + (size_t)(wrow + otile) * 512;

    if (tid < 128) sbias[tid] = bias[otile + tid];

    float acc[2][8][4] = {};

    unsigned a_base = (unsigned)((warp_o * 32 + (l & 15)) * 128 + (l >> 4) * 16);
    unsigned b_base = (unsigned)((warp_n * 64 + (l & 7) + ((l >> 4) << 3)) * 128
                                 + ((l >> 3) & 1) * 16);

    for (int c = 0; c < 8; c++) {
        int kk = c * 64;
        // ---- W staging: cp.async from pre-split bf16 ----
#pragma unroll
        for (int it = 0; it < 4; it++) {
            int e = tid + it * 256;
            int row = e >> 3, u = e & 7;
            unsigned soff = SWZ((unsigned)(row * 128 + u * 16));
            CPA16(base + S_WH + soff, (const char*)(Wh + (size_t)row * 512 + kk) + u * 16);
            CPA16(base + S_WL + soff, (const char*)(Wl + (size_t)row * 512 + kk) + u * 16);
        }
        CPA_COMMIT();
        // ---- X staging: bf16 repack (transpose k-pair into [n][kp]) ----
#pragma unroll
        for (int it = 0; it < 8; it++) {
            int e = tid + it * 256;            // 2048 items, each covers 2 n's
            int n2 = (e & 63) * 2, kp = e >> 6;
            size_t r0 = (size_t)(kk + 2 * kp) * N + ntile + n2;
            __nv_bfloat162 ah = *(const __nv_bfloat162*)(Xhb + r0);
            __nv_bfloat162 bh2 = *(const __nv_bfloat162*)(Xhb + r0 + N);
            __nv_bfloat162 al2 = *(const __nv_bfloat162*)(Xlb + r0);
            __nv_bfloat162 bl2 = *(const __nv_bfloat162*)(Xlb + r0 + N);
            unsigned o0 = SWZ((unsigned)(n2 * 128 + kp * 4));
            unsigned o1 = SWZ((unsigned)((n2 + 1) * 128 + kp * 4));
            __nv_bfloat162 p;
            p.x = ah.x; p.y = bh2.x; *(__nv_bfloat162*)(S + S_XH + o0) = p;
            p.x = ah.y; p.y = bh2.y; *(__nv_bfloat162*)(S + S_XH + o1) = p;
            p.x = al2.x; p.y = bl2.x; *(__nv_bfloat162*)(S + S_XL + o0) = p;
            p.x = al2.y; p.y = bl2.y; *(__nv_bfloat162*)(S + S_XL + o1) = p;
        }
        CPA_WAIT(0);
        __syncthreads();

#pragma unroll
        for (int ks = 0; ks < 4; ks++) {
            unsigned ko = ks * 32;
            unsigned ah[2][4], al[2][4];
#pragma unroll
            for (int mi = 0; mi < 2; mi++) {
                unsigned offA = SWZ(a_base + mi * 2048 + ko);
                LDMX4(ah[mi], base + S_WH + offA);
                LDMX4(al[mi], base + S_WL + offA);
            }
#pragma unroll
            for (int njp = 0; njp < 4; njp++) {
                unsigned offB = SWZ(b_base + njp * 2048 + ko);
                unsigned bh[4], bl[4];
                LDMX4(bh, base + S_XH + offB);
                LDMX4(bl, base + S_XL + offB);
#pragma unroll
                for (int mi = 0; mi < 2; mi++) {
                    MMA16816(acc[mi][njp * 2],     ah[mi], bh[0], bh[1]);
                    MMA16816(acc[mi][njp * 2],     ah[mi], bl[0], bl[1]);
                    MMA16816(acc[mi][njp * 2],     al[mi], bh[0], bh[1]);
                    MMA16816(acc[mi][njp * 2 + 1], ah[mi], bh[2], bh[3]);
                    MMA16816(acc[mi][njp * 2 + 1], ah[mi], bl[2], bl[3]);
                    MMA16816(acc[mi][njp * 2 + 1], al[mi], bh[2], bh[3]);
                }
            }
        }
        __syncthreads();
    }

    int r_base = warp_o * 32 + (l >> 2);
    int c_base = warp_n * 64 + 2 * (l & 3);
#pragma unroll
    for (int mi = 0; mi < 2; mi++)
#pragma unroll
        for (int nt = 0; nt < 8; nt++) {
            float* d0 = &Ds[(r_base + mi * 16) * 129 + c_base + nt * 8];
            d0[0]           = acc[mi][nt][0];
            d0[1]           = acc[mi][nt][1];
            d0[8 * 129]     = acc[mi][nt][2];
            d0[8 * 129 + 1] = acc[mi][nt][3];
        }
    __syncthreads();

    if (MODE == 0) {
        for (int e = tid; e < 16384; e += 256) {
            int d = e & 63, n = (e >> 6) & 127, h2 = e >> 13;
            int o = h2 * 64 + d;
            int h = (otile >> 6) + h2;
            float v = Ds[o * 129 + n] + sbias[o];
            size_t idx = ((size_t)(b * NHEAD + h) * NN + ntile + n) * HD + d;
            g_q[idx] = v;
            __nv_bfloat16 hv = __float2bfloat16(v);
            g_qh[idx] = hv;
            g_ql[idx] = __float2bfloat16(v - __bfloat162float(hv));
        }
    } else if (MODE == 1) {
        int h = otile >> 7;
        for (int e = tid; e < 16384; e += 256) {
            int d = e & 63, n = (e >> 6) & 127, half = e >> 13;
            int o = half * 64 + d;
            float* p = half ? g_fv : g_fk;
            p[((size_t)(b * NHEAD + h) * NN + ntile + n) * HD + d] = Ds[o * 129 + n] + sbias[o];
        }
    } else if (MODE == 3) {
        int h = otile >> 7;
        for (int e = tid; e < 16384; e += 256) {
            int d = e & 63, n = (e >> 6) & 127, half = e >> 13;
            int o = half * 64 + d;
            float* p = half ? g_v : g_k;
            p[((size_t)(b * NHEAD + h) * NUU + ntile + n) * HD + d] = Ds[o * 129 + n] + sbias[o];
        }
        for (int e = tid; e < 8192; e += 256) {     // K bf16 split [m][d]
            int d = e & 63, n = e >> 6;
            float v = Ds[d * 129 + n] + sbias[d];
            size_t idx = ((size_t)(b * NHEAD + h) * NUU + ntile + n) * HD + d;
            __nv_bfloat16 hv = __float2bfloat16(v);
            g_kh[idx] = hv;
            g_kl[idx] = __float2bfloat16(v - __bfloat162float(hv));
        }
        for (int e = tid; e < 8192; e += 256) {     // V^T bf16 split [d][m]
            int m = e & 127, r = e >> 7;
            float v = Ds[(64 + r) * 129 + m] + sbias[64 + r];
            size_t idx = ((size_t)(b * NHEAD + h) * HD + r) * NUU + ntile + m;
            __nv_bfloat16 hv = __float2bfloat16(v);
            g_vth[idx] = hv;
            g_vtl[idx] = __float2bfloat16(v - __bfloat162float(hv));
        }
    } else {
        for (int e = tid; e < 16384; e += 256) {
            int n = e & 127, o = e >> 7;
            out[((size_t)b * 512 + otile + o) * (size_t)NN + ntile + n] = Ds[o * 129 + n] + sbias[o];
        }
    }
}

// ---------------- flash attention: cp.async double-buffered K/V, 2 blocks/SM ---
#define FLASH_SMEM (98304 + 1024)

__global__ void __launch_bounds__(256, 2)
flash_mma()
{
    extern __shared__ char smraw[];
    unsigned sb = smem_u32(smraw);
    unsigned base = (sb + 1023) & ~1023u;
    const unsigned QH = 0, QL = 16384, KV0 = 32768;
    int tid = threadIdx.x, l = tid & 31, w = tid >> 5;
    int bh = blockIdx.y, ntile = blockIdx.x * 128;

    auto stageKV = [&](int buf, int mt) {
        unsigned bb = base + KV0 + (unsigned)buf * 32768;
        const char* kh = (const char*)(g_kh + ((size_t)bh * NUU + mt * 64) * HD);
        const char* kl = (const char*)(g_kl + ((size_t)bh * NUU + mt * 64) * HD);
#pragma unroll
        for (int it = 0; it < 2; it++) {
            int e = tid + it * 256;
            unsigned off = SWZ((unsigned)(e * 16));
            CPA16(bb + off,        kh + (size_t)e * 16);
            CPA16(bb + 8192 + off, kl + (size_t)e * 16);
        }
#pragma unroll
        for (int it = 0; it < 2; it++) {
            int e = tid + it * 256;
            int d = e >> 3, u = e & 7;
            unsigned off = SWZ((unsigned)(d * 128 + u * 16));
            CPA16(bb + 16384 + off,
                  (const char*)(g_vth + ((size_t)bh * HD + d) * NUU + mt * 64) + u * 16);
            CPA16(bb + 24576 + off,
                  (const char*)(g_vtl + ((size_t)bh * HD + d) * NUU + mt * 64) + u * 16);
        }
    };

    {
        const char* qh = (const char*)(g_qh + ((size_t)bh * NN + ntile) * HD);
        const char* ql = (const char*)(g_ql + ((size_t)bh * NN + ntile) * HD);
#pragma unroll
        for (int it = 0; it < 4; it++) {
            int e = tid + it * 256;
            unsigned off = SWZ((unsigned)(e * 16));
            CPA16(base + QH + off, qh + (size_t)e * 16);
            CPA16(base + QL + off, ql + (size_t)e * 16);
        }
        stageKV(0, 0);
        CPA_COMMIT();
    }

    float M0 = -1e30f, M1 = -1e30f, L0 = 0.f, L1 = 0.f;
    float acc[8][4] = {};
    unsigned a_base = (unsigned)((w * 16 + (l & 15)) * 128 + (l >> 4) * 16);
    unsigned b_base = (unsigned)(((l & 7) + ((l >> 4) << 3)) * 128 + ((l >> 3) & 1) * 16);

    for (int mt = 0; mt < 16; mt++) {
        if (mt < 15) { stageKV((mt + 1) & 1, mt + 1); CPA_COMMIT(); CPA_WAIT(1); }
        else CPA_WAIT(0);
        __syncthreads();
        unsigned bb = base + KV0 + (unsigned)(mt & 1) * 32768;
        const unsigned KH = bb, KL = bb + 8192, VH = bb + 16384, VL = bb + 24576;

        float s[8][4] = {};
#pragma unroll
        for (int ks = 0; ks < 4; ks++) {
            unsigned ko = ks * 32;
            unsigned aH[4], aL[4];
            LDMX4(aH, base + QH + SWZ(a_base + ko));
            LDMX4(aL, base + QL + SWZ(a_base + ko));
#pragma unroll
            for (int nj = 0; nj < 4; nj++) {
                unsigned offB = SWZ(b_base + nj * 2048 + ko);
                unsigned bH[4], bL[4];
                LDMX4(bH, KH + offB);
                LDMX4(bL, KL + offB);
                MMA16816(s[nj * 2],     aH, bH[0], bH[1]);
                MMA16816(s[nj * 2],     aH, bL[0], bL[1]);
                MMA16816(s[nj * 2],     aL, bH[0], bH[1]);
                MMA16816(s[nj * 2 + 1], aH, bH[2], bH[3]);
                MMA16816(s[nj * 2 + 1], aH, bL[2], bL[3]);
                MMA16816(s[nj * 2 + 1], aL, bH[2], bH[3]);
            }
        }

        float rm0 = -1e30f, rm1 = -1e30f;
#pragma unroll
        for (int j = 0; j < 8; j++) {
#pragma unroll
            for (int c = 0; c < 4; c++) s[j][c] *= SCALE_;
            rm0 = fmaxf(rm0, fmaxf(s[j][0], s[j][1]));
            rm1 = fmaxf(rm1, fmaxf(s[j][2], s[j][3]));
        }
        rm0 = fmaxf(rm0, __shfl_xor_sync(0xffffffffu, rm0, 1));
        rm0 = fmaxf(rm0, __shfl_xor_sync(0xffffffffu, rm0, 2));
        rm1 = fmaxf(rm1, __shfl_xor_sync(0xffffffffu, rm1, 1));
        rm1 = fmaxf(rm1, __shfl_xor_sync(0xffffffffu, rm1, 2));
        float Mn0 = fmaxf(M0, rm0), Mn1 = fmaxf(M1, rm1);
        float al0 = __expf(M0 - Mn0), al1 = __expf(M1 - Mn1);
        M0 = Mn0; M1 = Mn1;

        float rs0 = 0.f, rs1 = 0.f;
        unsigned phx[8], phy[8], plx[8], ply[8];
#pragma unroll
        for (int j = 0; j < 8; j++) {
            float p0 = __expf(s[j][0] - Mn0), p1 = __expf(s[j][1] - Mn0);
            float p2 = __expf(s[j][2] - Mn1), p3 = __expf(s[j][3] - Mn1);
            rs0 += p0 + p1; rs1 += p2 + p3;
            __nv_bfloat16 h0 = __float2bfloat16(p0), h1 = __float2bfloat16(p1);
            __nv_bfloat16 h2 = __float2bfloat16(p2), h3 = __float2bfloat16(p3);
            phx[j] = bfpack(h0, h1);
            phy[j] = bfpack(h2, h3);
            plx[j] = bfpack(__float2bfloat16(p0 - __bfloat162float(h0)),
                            __float2bfloat16(p1 - __bfloat162float(h1)));
            ply[j] = bfpack(__float2bfloat16(p2 - __bfloat162float(h2)),
                            __float2bfloat16(p3 - __bfloat162float(h3)));
        }
        rs0 += __shfl_xor_sync(0xffffffffu, rs0, 1);
        rs0 += __shfl_xor_sync(0xffffffffu, rs0, 2);
        rs1 += __shfl_xor_sync(0xffffffffu, rs1, 1);
        rs1 += __shfl_xor_sync(0xffffffffu, rs1, 2);
        L0 = L0 * al0 + rs0;
        L1 = L1 * al1 + rs1;
#pragma unroll
        for (int j = 0; j < 8; j++) {
            acc[j][0] *= al0; acc[j][1] *= al0;
            acc[j][2] *= al1; acc[j][3] *= al1;
        }

#pragma unroll
        for (int ks = 0; ks < 4; ks++) {
            unsigned aH[4] = {phx[2 * ks], phy[2 * ks], phx[2 * ks + 1], phy[2 * ks + 1]};
            unsigned aL[4] = {plx[2 * ks], ply[2 * ks], plx[2 * ks + 1], ply[2 * ks + 1]};
            unsigned ko = ks * 32;
#pragma unroll
            for (int nj = 0; nj < 4; nj++) {
                unsigned offB = SWZ(b_base + nj * 2048 + ko);
                unsigned vH[4], vL[4];
                LDMX4(vH, VH + offB);
                LDMX4(vL, VL + offB);
                MMA16816(acc[nj * 2],     aH, vH[0], vH[1]);
                MMA16816(acc[nj * 2],     aH, vL[0], vL[1]);
                MMA16816(acc[nj * 2],     aL, vH[0], vH[1]);
                MMA16816(acc[nj * 2 + 1], aH, vH[2], vH[3]);
                MMA16816(acc[nj * 2 + 1], aH, vL[2], vL[3]);
                MMA16816(acc[nj * 2 + 1], aL, vH[2], vH[3]);
            }
        }
        __syncthreads();
    }

    float inv0 = 1.f / L0, inv1 = 1.f / L1;
    int r0 = ntile + w * 16 + (l >> 2);
    float* C0 = &g_coarse[((size_t)bh * NN + r0) * HD];
    float* C1 = C0 + 8 * HD;
#pragma unroll
    for (int j = 0; j < 8; j++) {
        int col = j * 8 + (l & 3) * 2;
        *(float2*)&C0[col] = make_float2(acc[j][0] * inv0, acc[j][1] * inv0);
        *(float2*)&C1[col] = make_float2(acc[j][2] * inv1, acc[j][3] * inv1);
    }
}

// ---------------- heat ---------------------------------------------------------
__global__ void heat_kernel(const float* __restrict__ x)
{
    int bm = blockIdx.x;
    int b = bm >> 10, m = bm & 1023;
    int hu = m >> 5, wu = m & 31;
    int p00 = (2 * hu) * 64 + 2 * wu;
    int t = threadIdx.x;
    __shared__ float red[256];
    float s = 0.f;
    for (int c = t; c < NC; c += 256) {
        const float* xp = x + ((size_t)b * NC + c) * NN;
        s += xp[p00] + xp[p00 + 1] + xp[p00 + 64] + xp[p00 + 65];
    }
    red[t] = s; __syncthreads();
    for (int off = 128; off; off >>= 1) {
        if (t < off) red[t] += red[t + off];
        __syncthreads();
    }
    if (t == 0) g_heat[bm] = red[0] * (1.f / 2048.f);
}

// ---------------- qmean (1024 threads) ------------------------------------------
__global__ void qmean_kernel()
{
    int bh = blockIdx.x;
    int t = threadIdx.x;
    int d = t & 63, seg = t >> 6;
    float s = 0.f;
    const float* Q = g_q + (size_t)bh * NN * HD;
    for (int n = seg * 256; n < seg * 256 + 256; n++) s += Q[(size_t)n * HD + d];
    __shared__ float red[1024];
    red[t] = s; __syncthreads();
    if (seg == 0) {
        float a = 0.f;
#pragma unroll
        for (int i = 0; i < 16; i++) a += red[i * 64 + d];
        g_qmean[bh * HD + d] = a * (1.f / (float)NN);
    }
}

// ---------------- topk ---------------------------------------------------------
__global__ void topk_kernel(const float* __restrict__ gumbel)
{
    int bh = blockIdx.x;
    int b = bh >> 3;
    int t = threadIdx.x;
    __shared__ float s[NUU];
    __shared__ float qm[HD];
    __shared__ float rv[256];
    __shared__ int   ri[256];
    if (t < HD) qm[t] = g_qmean[bh * HD + t];
    __syncthreads();
    for (int m = t; m < NUU; m += 256) {
        const float* kp = g_k + ((size_t)bh * NUU + m) * HD;
        float dot = 0.f;
#pragma unroll
        for (int d = 0; d < HD; d++) dot += qm[d] * kp[d];
        s[m] = dot * SCALE_ * g_heat[b * NUU + m] + gumbel[(size_t)bh * NUU + m];
    }
    __syncthreads();
    for (int it = 0; it < 16; it++) {
        float bv = -1e30f; int bi = 0x7fffffff;
        for (int m = t; m < NUU; m += 256) {
            float v = s[m];
            if (v > bv || (v == bv && m < bi)) { bv = v; bi = m; }
        }
        rv[t] = bv; ri[t] = bi; __syncthreads();
        for (int off = 128; off; off >>= 1) {
            if (t < off) {
                float v2 = rv[t + off]; int i2 = ri[t + off];
                if (v2 > rv[t] || (v2 == rv[t] && i2 < ri[t])) { rv[t] = v2; ri[t] = i2; }
            }
            __syncthreads();
        }
        if (t == 0) {
            int m = ri[0];
            s[m] = -1e38f;
            int hi = (m >> 5) * 2, wi = (m & 31) * 2;
            int base = hi * 64 + wi;
            g_idxf[bh * 64 +       it] = base;
            g_idxf[bh * 64 + 16 +  it] = base + 1;
            g_idxf[bh * 64 + 32 +  it] = base + 64;
            g_idxf[bh * 64 + 48 +  it] = base + 65;
        }
        __syncthreads();
    }
}

// ---------------- fine attention + gate + blend (round-8 version) ---------------
struct FineSmem {
    float Ks[64][65];
    float Vs[64][64];
    float Gw[128][64];
    float Os[64][65];
    int   idx[64];
    float gb[64];
};

__global__ void fine_kernel(const float* __restrict__ gate_w, const float* __restrict__ gate_b)
{
    extern __shared__ char smem_raw[];
    FineSmem* S = reinterpret_cast<FineSmem*>(smem_raw);
    int bh = blockIdx.y;
    int b = bh >> 3, h = bh & 7;
    int ntile = blockIdx.x * 64;
    int t = threadIdx.x;

    if (t < 64) { S->idx[t] = g_idxf[bh * 64 + t]; S->gb[t] = gate_b[t]; }
    for (int e = t; e < 8192; e += 256) {
        int o = e >> 7, c = e & 127;
        S->Gw[c][o] = gate_w[e];
    }
    __syncthreads();
    for (int e = t; e < 4096; e += 256) {
        int m = e >> 6, d = e & 63;
        size_t src = ((size_t)bh * NN + S->idx[m]) * HD + d;
        S->Ks[m][d] = g_fk[src];
        S->Vs[m][d] = g_fv[src];
    }
    __syncthreads();

    int w = t >> 5, l = t & 31;
    for (int qi = 0; qi < 8; qi++) {
        int n = ntile + w * 8 + qi;
        const float* qp = g_q + ((size_t)bh * NN + n) * HD;
        float q0 = qp[l], q1 = qp[l + 32];
        float s0 = 0.f, s1 = 0.f;
#pragma unroll
        for (int d = 0; d < 64; d++) {
            float qd = __shfl_sync(0xffffffffu, d < 32 ? q0 : q1, d & 31);
            s0 += qd * S->Ks[l][d];
            s1 += qd * S->Ks[l + 32][d];
        }
        s0 *= SCALE_; s1 *= SCALE_;
        float mx = fmaxf(s0, s1);
#pragma unroll
        for (int off = 16; off; off >>= 1) mx = fmaxf(mx, __shfl_xor_sync(0xffffffffu, mx, off));
        float p0 = __expf(s0 - mx), p1 = __expf(s1 - mx);
        float sm = p0 + p1;
#pragma unroll
        for (int off = 16; off; off >>= 1) sm += __shfl_xor_sync(0xffffffffu, sm, off);
        float inv = 1.f / sm;
        p0 *= inv; p1 *= inv;

        float r0 = 0.f, r1 = 0.f;
#pragma unroll
        for (int m = 0; m < 64; m++) {
            float pm = __shfl_sync(0xffffffffu, m < 32 ? p0 : p1, m & 31);
            r0 += pm * S->Vs[m][l];
            r1 += pm * S->Vs[m][l + 32];
        }
        const float* cp = g_coarse + ((size_t)bh * NN + n) * HD;
        float c0 = cp[l], c1 = cp[l + 32];

        float g0 = S->gb[l], g1 = S->gb[l + 32];
#pragma unroll
        for (int c = 0; c < 64; c++) {
            float cv = __shfl_sync(0xffffffffu, c < 32 ? c0 : c1, c & 31);
            g0 += cv * S->Gw[c][l];
            g1 += cv * S->Gw[c][l + 32];
        }
#pragma unroll
        for (int c = 0; c < 64; c++) {
            float rvv = __shfl_sync(0xffffffffu, c < 32 ? r0 : r1, c & 31);
            g0 += rvv * S->Gw[64 + c][l];
            g1 += rvv * S->Gw[64 + c][l + 32];
        }
        g0 = 1.f / (1.f + __expf(-g0));
        g1 = 1.f / (1.f + __expf(-g1));
        int nl = w * 8 + qi;
        S->Os[l][nl]      = g0 * r0 + (1.f - g0) * c0;
        S->Os[l + 32][nl] = g1 * r1 + (1.f - g1) * c1;
    }
    __syncthreads();
    for (int e = t; e < 4096; e += 256) {
        int d = e >> 6, nl = e & 63;
        g_xsum[((size_t)b * NC + h * 64 + d) * NN + ntile + nl] = S->Os[d][nl];
    }
}

// ---------------- fused depthwise 7x7 conv + bilinear upsample-add -------------
__global__ void pe_bilinear(const float* __restrict__ pe_w, const float* __restrict__ pe_b)
{
    int bc = blockIdx.x;
    int b = bc >> 9, c = bc & 511;
    int h = c >> 6, d = c & 63;
    __shared__ float img[1024];
    __shared__ float pet[1024];
    __shared__ float wt[49];
    int t = threadIdx.x;
    for (int p = t; p < 1024; p += 256)
        img[p] = g_v[((size_t)(b * NHEAD + h) * NUU + p) * HD + d];
    if (t < 49) wt[t] = pe_w[c * 49 + t];
    __syncthreads();
    float bias = pe_b[c];
    for (int p = t; p < 1024; p += 256) {
        int y = p >> 5, xx0 = p & 31;
        float s = bias;
#pragma unroll
        for (int ky = 0; ky < 7; ky++) {
            int yy = y + ky - 3;
            if (yy < 0 || yy > 31) continue;
#pragma unroll
            for (int kx = 0; kx < 7; kx++) {
                int xx = xx0 + kx - 3;
                if (xx < 0 || xx > 31) continue;
                s += wt[ky * 7 + kx] * img[yy * 32 + xx];
            }
        }
        pet[p] = s;
    }
    __syncthreads();
    for (int p = t; p < 4096; p += 256) {
        int i = p >> 6, j = p & 63;
        int ti = i >> 1, tj = j >> 1;
        int y0, y1, x0, x1; float wy0, wy1, wx0, wx1;
        if (i & 1) { y0 = ti; y1 = min(ti + 1, 31); wy0 = 0.75f; wy1 = 0.25f; }
        else       { y0 = max(ti - 1, 0); y1 = ti;  wy0 = 0.25f; wy1 = 0.75f; }
        if (j & 1) { x0 = tj; x1 = min(tj + 1, 31); wx0 = 0.75f; wx1 = 0.25f; }
        else       { x0 = max(tj - 1, 0); x1 = tj;  wx0 = 0.25f; wx1 = 0.75f; }
        float v = wy0 * (wx0 * pet[y0 * 32 + x0] + wx1 * pet[y0 * 32 + x1])
                + wy1 * (wx0 * pet[y1 * 32 + x0] + wx1 * pet[y1 * 32 + x1]);
        g_xsum[(size_t)bc * 4096 + p] += v;
    }
}

// ---------------- launch ---------------------------------------------------------
extern "C" void kernel_launch(void* const* d_in, const int* in_sizes, int n_in,
                              void* d_out, int out_size)
{
    const float* x      = (const float*)d_in[0];
    const float* upper  = (const float*)d_in[1];
    const float* gumbel = (const float*)d_in[2];
    const float* q_w    = (const float*)d_in[3];
    const float* q_b    = (const float*)d_in[4];
    const float* kv_w   = (const float*)d_in[5];
    const float* kv_b   = (const float*)d_in[6];
    const float* proj_w = (const float*)d_in[7];
    const float* proj_b = (const float*)d_in[8];
    const float* pe_w   = (const float*)d_in[9];
    const float* pe_b   = (const float*)d_in[10];
    const float* gate_w = (const float*)d_in[11];
    const float* gate_b = (const float*)d_in[12];
    float* out = (float*)d_out;

    cudaFuncSetAttribute(fine_kernel, cudaFuncAttributeMaxDynamicSharedMemorySize,
                         (int)sizeof(FineSmem));
    cudaFuncSetAttribute(flash_mma, cudaFuncAttributeMaxDynamicSharedMemorySize, FLASH_SMEM);
    cudaFuncSetAttribute(conv_mma<0>, cudaFuncAttributeMaxDynamicSharedMemorySize, CONV_SMEM);
    cudaFuncSetAttribute(conv_mma<1>, cudaFuncAttributeMaxDynamicSharedMemorySize, CONV_SMEM);
    cudaFuncSetAttribute(conv_mma<2>, cudaFuncAttributeMaxDynamicSharedMemorySize, CONV_SMEM);
    cudaFuncSetAttribute(conv_mma<3>, cudaFuncAttributeMaxDynamicSharedMemorySize, CONV_SMEM);

    dim3 blk(256);

    split_weights<<<2048, blk>>>(q_w, kv_w, proj_w);
    split_f32<0><<<(NB * NC * NN / 4 + 255) / 256, blk>>>(x, NB * NC * NN / 4);
    split_f32<1><<<(NB * NC * NUU / 4 + 255) / 256, blk>>>(upper, NB * NC * NUU / 4);

    conv_mma<0><<<dim3(NN / 128,  512 / 128, NB), blk, CONV_SMEM>>>(0, q_b, nullptr, NN);
    conv_mma<3><<<dim3(NUU / 128, 1024 / 128, NB), blk, CONV_SMEM>>>(512, kv_b, nullptr, NUU);

    flash_mma<<<dim3(NN / 128, NB * NHEAD), blk, FLASH_SMEM>>>();

    conv_mma<1><<<dim3(NN / 128, 1024 / 128, NB), blk, CONV_SMEM>>>(512, kv_b, nullptr, NN);

    heat_kernel<<<NB * NUU, blk>>>(x);
    qmean_kernel<<<NB * NHEAD, 1024>>>();
    topk_kernel<<<NB * NHEAD, blk>>>(gumbel);

    fine_kernel<<<dim3(NN / 64, NB * NHEAD), blk, sizeof(FineSmem)>>>(gate_w, gate_b);

    pe_bilinear<<<NB * NC, blk>>>(pe_w, pe_b);

    split_f32<2><<<(NB * NC * NN / 4 + 255) / 256, blk>>>(nullptr, NB * NC * NN / 4);
    conv_mma<2><<<dim3(NN / 128, 512 / 128, NB), blk, CONV_SMEM>>>(1536, proj_b, out, NN);
}

// round 15
// speedup vs baseline: 1.0689x; 1.0689x over previous
#include <cuda_runtime.h>
#include <cuda_bf16.h>
#include <cstdint>

#define NB   2
#define NC   512
#define NN   4096
#define NUU  1024
#define NHEAD 8
#define HD   64
#define SCALE_ 0.125f

// ---------------- mma.sync helpers --------------------------------------------
__device__ __forceinline__ unsigned smem_u32(const void* p) {
    unsigned a;
    asm("{ .reg .u64 t; cvta.to.shared.u64 t, %1; cvt.u32.u64 %0, t; }" : "=r"(a) : "l"(p));
    return a;
}
#define SWZ(o) ((o) ^ (((o) >> 3) & 0x70))

#define LDMX4(r, addr) \
    asm volatile("ldmatrix.sync.aligned.m8n8.x4.shared.b16 {%0,%1,%2,%3},[%4];" \
        : "=r"((r)[0]), "=r"((r)[1]), "=r"((r)[2]), "=r"((r)[3]) : "r"(addr))

#define MMA16816(d, a, b0, b1) \
    asm volatile("mma.sync.aligned.m16n8k16.row.col.f32.bf16.bf16.f32 " \
        "{%0,%1,%2,%3},{%4,%5,%6,%7},{%8,%9},{%0,%1,%2,%3};" \
        : "+f"((d)[0]), "+f"((d)[1]), "+f"((d)[2]), "+f"((d)[3]) \
        : "r"((a)[0]), "r"((a)[1]), "r"((a)[2]), "r"((a)[3]), "r"(b0), "r"(b1))

#define CPA16(dst, src) \
    asm volatile("cp.async.cg.shared.global [%0],[%1],16;" :: "r"(dst), "l"(src))
#define CPA_COMMIT() asm volatile("cp.async.commit_group;" ::: "memory")
#define CPA_WAIT(n)  asm volatile("cp.async.wait_group %0;" :: "n"(n) : "memory")

__device__ __forceinline__ unsigned bfpack(__nv_bfloat16 a, __nv_bfloat16 b) {
    __nv_bfloat162 t(a, b); return *(unsigned*)&t;
}

// ---------------- scratch (device globals) ------------------------------------
__device__ float g_q     [NB*NHEAD*NN*HD];        // [b,h,n,d]
__device__ float g_fk    [NB*NHEAD*NN*HD];
__device__ float g_fv    [NB*NHEAD*NN*HD];
__device__ float g_k     [NB*NHEAD*NUU*HD];       // [b,h,m,d]
__device__ float g_v     [NB*NHEAD*NUU*HD];
__device__ float g_coarse[NB*NHEAD*NN*HD];
__device__ float g_xsum  [NB*NC*NN];              // x_out (+ v_pe) in [b,c,n]
__device__ float g_heat  [NB*NUU];
__device__ float g_qmean [NB*NHEAD*HD];
__device__ int   g_idxf  [NB*NHEAD*64];
// pre-split bf16 weights: rows 0..511 = q_w, 512..1535 = kv_w, 1536..2047 = proj_w
__device__ __nv_bfloat16 g_wh [2048*512], g_wl [2048*512];
// pre-split bf16 operands for flash (produced by conv epilogues)
__device__ __nv_bfloat16 g_qh [NB*NHEAD*NN*HD],  g_ql [NB*NHEAD*NN*HD];
__device__ __nv_bfloat16 g_kh [NB*NHEAD*NUU*HD], g_kl [NB*NHEAD*NUU*HD];
__device__ __nv_bfloat16 g_vth[NB*NHEAD*HD*NUU], g_vtl[NB*NHEAD*HD*NUU];

// ---------------- weight pre-split ---------------------------------------------
__global__ void split_weights(const float* __restrict__ qw, const float* __restrict__ kvw,
                              const float* __restrict__ pw)
{
    int r = blockIdx.x;
    const float* src = r < 512 ? qw + (size_t)r * 512
                     : r < 1536 ? kvw + (size_t)(r - 512) * 512
                                : pw + (size_t)(r - 1536) * 512;
    for (int c = threadIdx.x; c < 512; c += 256) {
        float v = src[c];
        __nv_bfloat16 h = __float2bfloat16(v);
        g_wh[(size_t)r * 512 + c] = h;
        g_wl[(size_t)r * 512 + c] = __float2bfloat16(v - __bfloat162float(h));
    }
}

// ---------------- conv1x1 GEMM via mma.sync bf16-split (round-12, 723 µs) ------
#define CONV_SMEM (66048 + 1024)

template<int MODE>
__global__ void __launch_bounds__(256, 2)
conv_mma(const float* __restrict__ X, int wrow,
         const float* __restrict__ bias, float* __restrict__ out, int N)
{
    extern __shared__ char smraw[];
    unsigned sb = smem_u32(smraw);
    unsigned base = (sb + 1023) & ~1023u;
    char* S = smraw + (base - sb);
    const unsigned S_WH = 0, S_WL = 16384, S_XH = 32768, S_XL = 49152;
    float* Ds = (float*)S;
    __shared__ float sbias[128];

    int tid = threadIdx.x, l = tid & 31, wid = tid >> 5;
    int warp_o = wid & 3, warp_n = wid >> 2;
    int b = blockIdx.z, otile = blockIdx.y * 128, ntile = blockIdx.x * 128;
    const float* Xb = (MODE == 2 ? g_xsum : X) + (size_t)b * 512 * N;
    const __nv_bfloat16* Wh = g_wh + (size_t)(wrow + otile) * 512;
    const __nv_bfloat16* Wl = g_wl + (size_t)(wrow + otile) * 512;

    if (tid < 128) sbias[tid] = bias[otile + tid];

    float acc[2][8][4] = {};

    unsigned a_base = (unsigned)((warp_o * 32 + (l & 15)) * 128 + (l >> 4) * 16);
    unsigned b_base = (unsigned)((warp_n * 64 + (l & 7) + ((l >> 4) << 3)) * 128
                                 + ((l >> 3) & 1) * 16);

    for (int c = 0; c < 8; c++) {
        int kk = c * 64;
#pragma unroll
        for (int it = 0; it < 4; it++) {
            int e = tid + it * 256;
            int row = e >> 3, u = e & 7;
            unsigned soff = SWZ((unsigned)(row * 128 + u * 16));
            CPA16(base + S_WH + soff, (const char*)(Wh + (size_t)row * 512 + kk) + u * 16);
            CPA16(base + S_WL + soff, (const char*)(Wl + (size_t)row * 512 + kk) + u * 16);
        }
        CPA_COMMIT();
#pragma unroll
        for (int it = 0; it < 16; it++) {
            int e = tid + it * 256;
            int n = e & 127, kp = e >> 7;
            float x0 = Xb[(size_t)(kk + 2 * kp) * N + ntile + n];
            float x1 = Xb[(size_t)(kk + 2 * kp + 1) * N + ntile + n];
            __nv_bfloat16 h0 = __float2bfloat16(x0);
            __nv_bfloat16 h1 = __float2bfloat16(x1);
            __nv_bfloat162 hp; hp.x = h0; hp.y = h1;
            __nv_bfloat162 lp;
            lp.x = __float2bfloat16(x0 - __bfloat162float(h0));
            lp.y = __float2bfloat16(x1 - __bfloat162float(h1));
            unsigned off = SWZ((unsigned)(n * 128 + kp * 4));
            *(__nv_bfloat162*)(S + S_XH + off) = hp;
            *(__nv_bfloat162*)(S + S_XL + off) = lp;
        }
        CPA_WAIT(0);
        __syncthreads();

#pragma unroll
        for (int ks = 0; ks < 4; ks++) {
            unsigned ko = ks * 32;
            unsigned ah[2][4], al[2][4];
#pragma unroll
            for (int mi = 0; mi < 2; mi++) {
                unsigned offA = SWZ(a_base + mi * 2048 + ko);
                LDMX4(ah[mi], base + S_WH + offA);
                LDMX4(al[mi], base + S_WL + offA);
            }
#pragma unroll
            for (int njp = 0; njp < 4; njp++) {
                unsigned offB = SWZ(b_base + njp * 2048 + ko);
                unsigned bh[4], bl[4];
                LDMX4(bh, base + S_XH + offB);
                LDMX4(bl, base + S_XL + offB);
#pragma unroll
                for (int mi = 0; mi < 2; mi++) {
                    MMA16816(acc[mi][njp * 2],     ah[mi], bh[0], bh[1]);
                    MMA16816(acc[mi][njp * 2],     ah[mi], bl[0], bl[1]);
                    MMA16816(acc[mi][njp * 2],     al[mi], bh[0], bh[1]);
                    MMA16816(acc[mi][njp * 2 + 1], ah[mi], bh[2], bh[3]);
                    MMA16816(acc[mi][njp * 2 + 1], ah[mi], bl[2], bl[3]);
                    MMA16816(acc[mi][njp * 2 + 1], al[mi], bh[2], bh[3]);
                }
            }
        }
        __syncthreads();
    }

    int r_base = warp_o * 32 + (l >> 2);
    int c_base = warp_n * 64 + 2 * (l & 3);
#pragma unroll
    for (int mi = 0; mi < 2; mi++)
#pragma unroll
        for (int nt = 0; nt < 8; nt++) {
            float* d0 = &Ds[(r_base + mi * 16) * 129 + c_base + nt * 8];
            d0[0]           = acc[mi][nt][0];
            d0[1]           = acc[mi][nt][1];
            d0[8 * 129]     = acc[mi][nt][2];
            d0[8 * 129 + 1] = acc[mi][nt][3];
        }
    __syncthreads();

    if (MODE == 0) {
        for (int e = tid; e < 16384; e += 256) {
            int d = e & 63, n = (e >> 6) & 127, h2 = e >> 13;
            int o = h2 * 64 + d;
            int h = (otile >> 6) + h2;
            float v = Ds[o * 129 + n] + sbias[o];
            size_t idx = ((size_t)(b * NHEAD + h) * NN + ntile + n) * HD + d;
            g_q[idx] = v;
            __nv_bfloat16 hv = __float2bfloat16(v);
            g_qh[idx] = hv;
            g_ql[idx] = __float2bfloat16(v - __bfloat162float(hv));
        }
    } else if (MODE == 1) {
        int h = otile >> 7;
        for (int e = tid; e < 16384; e += 256) {
            int d = e & 63, n = (e >> 6) & 127, half = e >> 13;
            int o = half * 64 + d;
            float* p = half ? g_fv : g_fk;
            p[((size_t)(b * NHEAD + h) * NN + ntile + n) * HD + d] = Ds[o * 129 + n] + sbias[o];
        }
    } else if (MODE == 3) {
        int h = otile >> 7;
        for (int e = tid; e < 16384; e += 256) {
            int d = e & 63, n = (e >> 6) & 127, half = e >> 13;
            int o = half * 64 + d;
            float* p = half ? g_v : g_k;
            p[((size_t)(b * NHEAD + h) * NUU + ntile + n) * HD + d] = Ds[o * 129 + n] + sbias[o];
        }
        for (int e = tid; e < 8192; e += 256) {     // K bf16 split [m][d]
            int d = e & 63, n = e >> 6;
            float v = Ds[d * 129 + n] + sbias[d];
            size_t idx = ((size_t)(b * NHEAD + h) * NUU + ntile + n) * HD + d;
            __nv_bfloat16 hv = __float2bfloat16(v);
            g_kh[idx] = hv;
            g_kl[idx] = __float2bfloat16(v - __bfloat162float(hv));
        }
        for (int e = tid; e < 8192; e += 256) {     // V^T bf16 split [d][m]
            int m = e & 127, r = e >> 7;
            float v = Ds[(64 + r) * 129 + m] + sbias[64 + r];
            size_t idx = ((size_t)(b * NHEAD + h) * HD + r) * NUU + ntile + m;
            __nv_bfloat16 hv = __float2bfloat16(v);
            g_vth[idx] = hv;
            g_vtl[idx] = __float2bfloat16(v - __bfloat162float(hv));
        }
    } else {
        for (int e = tid; e < 16384; e += 256) {
            int n = e & 127, o = e >> 7;
            out[((size_t)b * 512 + otile + o) * (size_t)NN + ntile + n] = Ds[o * 129 + n] + sbias[o];
        }
    }
}

// ---------------- flash attention: cp.async double-buffered K/V, 2 blocks/SM ---
#define FLASH_SMEM (98304 + 1024)

__global__ void __launch_bounds__(256, 2)
flash_mma()
{
    extern __shared__ char smraw[];
    unsigned sb = smem_u32(smraw);
    unsigned base = (sb + 1023) & ~1023u;
    const unsigned QH = 0, QL = 16384, KV0 = 32768;
    int tid = threadIdx.x, l = tid & 31, w = tid >> 5;
    int bh = blockIdx.y, ntile = blockIdx.x * 128;

    auto stageKV = [&](int buf, int mt) {
        unsigned bb = base + KV0 + (unsigned)buf * 32768;
        const char* kh = (const char*)(g_kh + ((size_t)bh * NUU + mt * 64) * HD);
        const char* kl = (const char*)(g_kl + ((size_t)bh * NUU + mt * 64) * HD);
#pragma unroll
        for (int it = 0; it < 2; it++) {
            int e = tid + it * 256;
            unsigned off = SWZ((unsigned)(e * 16));
            CPA16(bb + off,        kh + (size_t)e * 16);
            CPA16(bb + 8192 + off, kl + (size_t)e * 16);
        }
#pragma unroll
        for (int it = 0; it < 2; it++) {
            int e = tid + it * 256;
            int d = e >> 3, u = e & 7;
            unsigned off = SWZ((unsigned)(d * 128 + u * 16));
            CPA16(bb + 16384 + off,
                  (const char*)(g_vth + ((size_t)bh * HD + d) * NUU + mt * 64) + u * 16);
            CPA16(bb + 24576 + off,
                  (const char*)(g_vtl + ((size_t)bh * HD + d) * NUU + mt * 64) + u * 16);
        }
    };

    {
        const char* qh = (const char*)(g_qh + ((size_t)bh * NN + ntile) * HD);
        const char* ql = (const char*)(g_ql + ((size_t)bh * NN + ntile) * HD);
#pragma unroll
        for (int it = 0; it < 4; it++) {
            int e = tid + it * 256;
            unsigned off = SWZ((unsigned)(e * 16));
            CPA16(base + QH + off, qh + (size_t)e * 16);
            CPA16(base + QL + off, ql + (size_t)e * 16);
        }
        stageKV(0, 0);
        CPA_COMMIT();
    }

    float M0 = -1e30f, M1 = -1e30f, L0 = 0.f, L1 = 0.f;
    float acc[8][4] = {};
    unsigned a_base = (unsigned)((w * 16 + (l & 15)) * 128 + (l >> 4) * 16);
    unsigned b_base = (unsigned)(((l & 7) + ((l >> 4) << 3)) * 128 + ((l >> 3) & 1) * 16);

    for (int mt = 0; mt < 16; mt++) {
        if (mt < 15) { stageKV((mt + 1) & 1, mt + 1); CPA_COMMIT(); CPA_WAIT(1); }
        else CPA_WAIT(0);
        __syncthreads();
        unsigned bb = base + KV0 + (unsigned)(mt & 1) * 32768;
        const unsigned KH = bb, KL = bb + 8192, VH = bb + 16384, VL = bb + 24576;

        float s[8][4] = {};
#pragma unroll
        for (int ks = 0; ks < 4; ks++) {
            unsigned ko = ks * 32;
            unsigned aH[4], aL[4];
            LDMX4(aH, base + QH + SWZ(a_base + ko));
            LDMX4(aL, base + QL + SWZ(a_base + ko));
#pragma unroll
            for (int nj = 0; nj < 4; nj++) {
                unsigned offB = SWZ(b_base + nj * 2048 + ko);
                unsigned bH[4], bL[4];
                LDMX4(bH, KH + offB);
                LDMX4(bL, KL + offB);
                MMA16816(s[nj * 2],     aH, bH[0], bH[1]);
                MMA16816(s[nj * 2],     aH, bL[0], bL[1]);
                MMA16816(s[nj * 2],     aL, bH[0], bH[1]);
                MMA16816(s[nj * 2 + 1], aH, bH[2], bH[3]);
                MMA16816(s[nj * 2 + 1], aH, bL[2], bL[3]);
                MMA16816(s[nj * 2 + 1], aL, bH[2], bH[3]);
            }
        }

        float rm0 = -1e30f, rm1 = -1e30f;
#pragma unroll
        for (int j = 0; j < 8; j++) {
#pragma unroll
            for (int c = 0; c < 4; c++) s[j][c] *= SCALE_;
            rm0 = fmaxf(rm0, fmaxf(s[j][0], s[j][1]));
            rm1 = fmaxf(rm1, fmaxf(s[j][2], s[j][3]));
        }
        rm0 = fmaxf(rm0, __shfl_xor_sync(0xffffffffu, rm0, 1));
        rm0 = fmaxf(rm0, __shfl_xor_sync(0xffffffffu, rm0, 2));
        rm1 = fmaxf(rm1, __shfl_xor_sync(0xffffffffu, rm1, 1));
        rm1 = fmaxf(rm1, __shfl_xor_sync(0xffffffffu, rm1, 2));
        float Mn0 = fmaxf(M0, rm0), Mn1 = fmaxf(M1, rm1);
        float al0 = __expf(M0 - Mn0), al1 = __expf(M1 - Mn1);
        M0 = Mn0; M1 = Mn1;

        float rs0 = 0.f, rs1 = 0.f;
        unsigned phx[8], phy[8], plx[8], ply[8];
#pragma unroll
        for (int j = 0; j < 8; j++) {
            float p0 = __expf(s[j][0] - Mn0), p1 = __expf(s[j][1] - Mn0);
            float p2 = __expf(s[j][2] - Mn1), p3 = __expf(s[j][3] - Mn1);
            rs0 += p0 + p1; rs1 += p2 + p3;
            __nv_bfloat16 h0 = __float2bfloat16(p0), h1 = __float2bfloat16(p1);
            __nv_bfloat16 h2 = __float2bfloat16(p2), h3 = __float2bfloat16(p3);
            phx[j] = bfpack(h0, h1);
            phy[j] = bfpack(h2, h3);
            plx[j] = bfpack(__float2bfloat16(p0 - __bfloat162float(h0)),
                            __float2bfloat16(p1 - __bfloat162float(h1)));
            ply[j] = bfpack(__float2bfloat16(p2 - __bfloat162float(h2)),
                            __float2bfloat16(p3 - __bfloat162float(h3)));
        }
        rs0 += __shfl_xor_sync(0xffffffffu, rs0, 1);
        rs0 += __shfl_xor_sync(0xffffffffu, rs0, 2);
        rs1 += __shfl_xor_sync(0xffffffffu, rs1, 1);
        rs1 += __shfl_xor_sync(0xffffffffu, rs1, 2);
        L0 = L0 * al0 + rs0;
        L1 = L1 * al1 + rs1;
#pragma unroll
        for (int j = 0; j < 8; j++) {
            acc[j][0] *= al0; acc[j][1] *= al0;
            acc[j][2] *= al1; acc[j][3] *= al1;
        }

#pragma unroll
        for (int ks = 0; ks < 4; ks++) {
            unsigned aH[4] = {phx[2 * ks], phy[2 * ks], phx[2 * ks + 1], phy[2 * ks + 1]};
            unsigned aL[4] = {plx[2 * ks], ply[2 * ks], plx[2 * ks + 1], ply[2 * ks + 1]};
            unsigned ko = ks * 32;
#pragma unroll
            for (int nj = 0; nj < 4; nj++) {
                unsigned offB = SWZ(b_base + nj * 2048 + ko);
                unsigned vH[4], vL[4];
                LDMX4(vH, VH + offB);
                LDMX4(vL, VL + offB);
                MMA16816(acc[nj * 2],     aH, vH[0], vH[1]);
                MMA16816(acc[nj * 2],     aH, vL[0], vL[1]);
                MMA16816(acc[nj * 2],     aL, vH[0], vH[1]);
                MMA16816(acc[nj * 2 + 1], aH, vH[2], vH[3]);
                MMA16816(acc[nj * 2 + 1], aH, vL[2], vL[3]);
                MMA16816(acc[nj * 2 + 1], aL, vH[2], vH[3]);
            }
        }
        __syncthreads();
    }

    float inv0 = 1.f / L0, inv1 = 1.f / L1;
    int r0 = ntile + w * 16 + (l >> 2);
    float* C0 = &g_coarse[((size_t)bh * NN + r0) * HD];
    float* C1 = C0 + 8 * HD;
#pragma unroll
    for (int j = 0; j < 8; j++) {
        int col = j * 8 + (l & 3) * 2;
        *(float2*)&C0[col] = make_float2(acc[j][0] * inv0, acc[j][1] * inv0);
        *(float2*)&C1[col] = make_float2(acc[j][2] * inv1, acc[j][3] * inv1);
    }
}

// ---------------- heat: coalesced, one block per (b, hu) -----------------------
__global__ void heat_kernel(const float* __restrict__ x)
{
    int bi = blockIdx.x;
    int b = bi >> 5, hu = bi & 31;
    int t = threadIdx.x;               // 1024 threads: 16 c-groups x (r, wu)
    int g = t >> 6, j = t & 63;
    int r = j >> 5, wu = j & 31;
    const float* xp = x + (size_t)b * NC * NN + (size_t)(2 * hu + r) * 64 + 2 * wu;
    float s = 0.f;
#pragma unroll 4
    for (int c = g * 32; c < g * 32 + 32; c++) {
        float2 v = *(const float2*)(xp + (size_t)c * NN);
        s += v.x + v.y;
    }
    __shared__ float red[1024];
    red[t] = s;
    __syncthreads();
    if (t < 32) {
        float a = 0.f;
#pragma unroll
        for (int gg = 0; gg < 16; gg++)
            a += red[gg * 64 + t] + red[gg * 64 + 32 + t];
        g_heat[b * NUU + hu * 32 + t] = a * (1.f / 2048.f);
    }
}

// ---------------- qmean (1024 threads) ------------------------------------------
__global__ void qmean_kernel()
{
    int bh = blockIdx.x;
    int t = threadIdx.x;
    int d = t & 63, seg = t >> 6;
    float s = 0.f;
    const float* Q = g_q + (size_t)bh * NN * HD;
    for (int n = seg * 256; n < seg * 256 + 256; n++) s += Q[(size_t)n * HD + d];
    __shared__ float red[1024];
    red[t] = s; __syncthreads();
    if (seg == 0) {
        float a = 0.f;
#pragma unroll
        for (int i = 0; i < 16; i++) a += red[i * 64 + d];
        g_qmean[bh * HD + d] = a * (1.f / (float)NN);
    }
}

// ---------------- topk ---------------------------------------------------------
__global__ void topk_kernel(const float* __restrict__ gumbel)
{
    int bh = blockIdx.x;
    int b = bh >> 3;
    int t = threadIdx.x;
    __shared__ float s[NUU];
    __shared__ float qm[HD];
    __shared__ float rv[256];
    __shared__ int   ri[256];
    if (t < HD) qm[t] = g_qmean[bh * HD + t];
    __syncthreads();
    for (int m = t; m < NUU; m += 256) {
        const float* kp = g_k + ((size_t)bh * NUU + m) * HD;
        float dot = 0.f;
#pragma unroll
        for (int d = 0; d < HD; d++) dot += qm[d] * kp[d];
        s[m] = dot * SCALE_ * g_heat[b * NUU + m] + gumbel[(size_t)bh * NUU + m];
    }
    __syncthreads();
    for (int it = 0; it < 16; it++) {
        float bv = -1e30f; int bi = 0x7fffffff;
        for (int m = t; m < NUU; m += 256) {
            float v = s[m];
            if (v > bv || (v == bv && m < bi)) { bv = v; bi = m; }
        }
        rv[t] = bv; ri[t] = bi; __syncthreads();
        for (int off = 128; off; off >>= 1) {
            if (t < off) {
                float v2 = rv[t + off]; int i2 = ri[t + off];
                if (v2 > rv[t] || (v2 == rv[t] && i2 < ri[t])) { rv[t] = v2; ri[t] = i2; }
            }
            __syncthreads();
        }
        if (t == 0) {
            int m = ri[0];
            s[m] = -1e38f;
            int hi = (m >> 5) * 2, wi = (m & 31) * 2;
            int base = hi * 64 + wi;
            g_idxf[bh * 64 +       it] = base;
            g_idxf[bh * 64 + 16 +  it] = base + 1;
            g_idxf[bh * 64 + 32 +  it] = base + 64;
            g_idxf[bh * 64 + 48 +  it] = base + 65;
        }
        __syncthreads();
    }
}

// ---------------- fine attention + gate + blend (round-8 version) ---------------
struct FineSmem {
    float Ks[64][65];
    float Vs[64][64];
    float Gw[128][64];
    float Os[64][65];
    int   idx[64];
    float gb[64];
};

__global__ void __launch_bounds__(256, 2)
fine_kernel(const float* __restrict__ gate_w, const float* __restrict__ gate_b)
{
    extern __shared__ char smem_raw[];
    FineSmem* S = reinterpret_cast<FineSmem*>(smem_raw);
    int bh = blockIdx.y;
    int b = bh >> 3, h = bh & 7;
    int ntile = blockIdx.x * 64;
    int t = threadIdx.x;

    if (t < 64) { S->idx[t] = g_idxf[bh * 64 + t]; S->gb[t] = gate_b[t]; }
    for (int e = t; e < 8192; e += 256) {
        int o = e >> 7, c = e & 127;
        S->Gw[c][o] = gate_w[e];
    }
    __syncthreads();
    for (int e = t; e < 4096; e += 256) {
        int m = e >> 6, d = e & 63;
        size_t src = ((size_t)bh * NN + S->idx[m]) * HD + d;
        S->Ks[m][d] = g_fk[src];
        S->Vs[m][d] = g_fv[src];
    }
    __syncthreads();

    int w = t >> 5, l = t & 31;
    for (int qi = 0; qi < 8; qi++) {
        int n = ntile + w * 8 + qi;
        const float* qp = g_q + ((size_t)bh * NN + n) * HD;
        float q0 = qp[l], q1 = qp[l + 32];
        float s0 = 0.f, s1 = 0.f;
#pragma unroll
        for (int d = 0; d < 64; d++) {
            float qd = __shfl_sync(0xffffffffu, d < 32 ? q0 : q1, d & 31);
            s0 += qd * S->Ks[l][d];
            s1 += qd * S->Ks[l + 32][d];
        }
        s0 *= SCALE_; s1 *= SCALE_;
        float mx = fmaxf(s0, s1);
#pragma unroll
        for (int off = 16; off; off >>= 1) mx = fmaxf(mx, __shfl_xor_sync(0xffffffffu, mx, off));
        float p0 = __expf(s0 - mx), p1 = __expf(s1 - mx);
        float sm = p0 + p1;
#pragma unroll
        for (int off = 16; off; off >>= 1) sm += __shfl_xor_sync(0xffffffffu, sm, off);
        float inv = 1.f / sm;
        p0 *= inv; p1 *= inv;

        float r0 = 0.f, r1 = 0.f;
#pragma unroll
        for (int m = 0; m < 64; m++) {
            float pm = __shfl_sync(0xffffffffu, m < 32 ? p0 : p1, m & 31);
            r0 += pm * S->Vs[m][l];
            r1 += pm * S->Vs[m][l + 32];
        }
        const float* cp = g_coarse + ((size_t)bh * NN + n) * HD;
        float c0 = cp[l], c1 = cp[l + 32];

        float g0 = S->gb[l], g1 = S->gb[l + 32];
#pragma unroll
        for (int c = 0; c < 64; c++) {
            float cv = __shfl_sync(0xffffffffu, c < 32 ? c0 : c1, c & 31);
            g0 += cv * S->Gw[c][l];
            g1 += cv * S->Gw[c][l + 32];
        }
#pragma unroll
        for (int c = 0; c < 64; c++) {
            float rvv = __shfl_sync(0xffffffffu, c < 32 ? r0 : r1, c & 31);
            g0 += rvv * S->Gw[64 + c][l];
            g1 += rvv * S->Gw[64 + c][l + 32];
        }
        g0 = 1.f / (1.f + __expf(-g0));
        g1 = 1.f / (1.f + __expf(-g1));
        int nl = w * 8 + qi;
        S->Os[l][nl]      = g0 * r0 + (1.f - g0) * c0;
        S->Os[l + 32][nl] = g1 * r1 + (1.f - g1) * c1;
    }
    __syncthreads();
    for (int e = t; e < 4096; e += 256) {
        int d = e >> 6, nl = e & 63;
        g_xsum[((size_t)b * NC + h * 64 + d) * NN + ntile + nl] = S->Os[d][nl];
    }
}

// ---------------- fused depthwise 7x7 conv + bilinear upsample-add -------------
__global__ void pe_bilinear(const float* __restrict__ pe_w, const float* __restrict__ pe_b)
{
    int bc = blockIdx.x;
    int b = bc >> 9, c = bc & 511;
    int h = c >> 6, d = c & 63;
    __shared__ float img[1024];
    __shared__ float pet[1024];
    __shared__ float wt[49];
    int t = threadIdx.x;
    for (int p = t; p < 1024; p += 256)
        img[p] = g_v[((size_t)(b * NHEAD + h) * NUU + p) * HD + d];
    if (t < 49) wt[t] = pe_w[c * 49 + t];
    __syncthreads();
    float bias = pe_b[c];
    for (int p = t; p < 1024; p += 256) {
        int y = p >> 5, xx0 = p & 31;
        float s = bias;
#pragma unroll
        for (int ky = 0; ky < 7; ky++) {
            int yy = y + ky - 3;
            if (yy < 0 || yy > 31) continue;
#pragma unroll
            for (int kx = 0; kx < 7; kx++) {
                int xx = xx0 + kx - 3;
                if (xx < 0 || xx > 31) continue;
                s += wt[ky * 7 + kx] * img[yy * 32 + xx];
            }
        }
        pet[p] = s;
    }
    __syncthreads();
    for (int p = t; p < 4096; p += 256) {
        int i = p >> 6, j = p & 63;
        int ti = i >> 1, tj = j >> 1;
        int y0, y1, x0, x1; float wy0, wy1, wx0, wx1;
        if (i & 1) { y0 = ti; y1 = min(ti + 1, 31); wy0 = 0.75f; wy1 = 0.25f; }
        else       { y0 = max(ti - 1, 0); y1 = ti;  wy0 = 0.25f; wy1 = 0.75f; }
        if (j & 1) { x0 = tj; x1 = min(tj + 1, 31); wx0 = 0.75f; wx1 = 0.25f; }
        else       { x0 = max(tj - 1, 0); x1 = tj;  wx0 = 0.25f; wx1 = 0.75f; }
        float v = wy0 * (wx0 * pet[y0 * 32 + x0] + wx1 * pet[y0 * 32 + x1])
                + wy1 * (wx0 * pet[y1 * 32 + x0] + wx1 * pet[y1 * 32 + x1]);
        g_xsum[(size_t)bc * 4096 + p] += v;
    }
}

// ---------------- launch ---------------------------------------------------------
extern "C" void kernel_launch(void* const* d_in, const int* in_sizes, int n_in,
                              void* d_out, int out_size)
{
    const float* x      = (const float*)d_in[0];
    const float* upper  = (const float*)d_in[1];
    const float* gumbel = (const float*)d_in[2];
    const float* q_w    = (const float*)d_in[3];
    const float* q_b    = (const float*)d_in[4];
    const float* kv_w   = (const float*)d_in[5];
    const float* kv_b   = (const float*)d_in[6];
    const float* proj_w = (const float*)d_in[7];
    const float* proj_b = (const float*)d_in[8];
    const float* pe_w   = (const float*)d_in[9];
    const float* pe_b   = (const float*)d_in[10];
    const float* gate_w = (const float*)d_in[11];
    const float* gate_b = (const float*)d_in[12];
    float* out = (float*)d_out;

    cudaFuncSetAttribute(fine_kernel, cudaFuncAttributeMaxDynamicSharedMemorySize,
                         (int)sizeof(FineSmem));
    cudaFuncSetAttribute(flash_mma, cudaFuncAttributeMaxDynamicSharedMemorySize, FLASH_SMEM);
    cudaFuncSetAttribute(conv_mma<0>, cudaFuncAttributeMaxDynamicSharedMemorySize, CONV_SMEM);
    cudaFuncSetAttribute(conv_mma<1>, cudaFuncAttributeMaxDynamicSharedMemorySize, CONV_SMEM);
    cudaFuncSetAttribute(conv_mma<2>, cudaFuncAttributeMaxDynamicSharedMemorySize, CONV_SMEM);
    cudaFuncSetAttribute(conv_mma<3>, cudaFuncAttributeMaxDynamicSharedMemorySize, CONV_SMEM);

    dim3 blk(256);

    split_weights<<<2048, blk>>>(q_w, kv_w, proj_w);

    conv_mma<0><<<dim3(NN / 128,  512 / 128, NB), blk, CONV_SMEM>>>(x, 0, q_b, nullptr, NN);
    conv_mma<3><<<dim3(NUU / 128, 1024 / 128, NB), blk, CONV_SMEM>>>(upper, 512, kv_b, nullptr, NUU);

    flash_mma<<<dim3(NN / 128, NB * NHEAD), blk, FLASH_SMEM>>>();

    conv_mma<1><<<dim3(NN / 128, 1024 / 128, NB), blk, CONV_SMEM>>>(x, 512, kv_b, nullptr, NN);

    heat_kernel<<<NB * 32, 1024>>>(x);
    qmean_kernel<<<NB * NHEAD, 1024>>>();
    topk_kernel<<<NB * NHEAD, blk>>>(gumbel);

    fine_kernel<<<dim3(NN / 64, NB * NHEAD), blk, sizeof(FineSmem)>>>(gate_w, gate_b);

    pe_bilinear<<<NB * NC, blk>>>(pe_w, pe_b);

    conv_mma<2><<<dim3(NN / 128, 512 / 128, NB), blk, CONV_SMEM>>>(nullptr, 1536, proj_b, out, NN);
}

// round 16
// speedup vs baseline: 1.2509x; 1.1702x over previous
#include <cuda_runtime.h>
#include <cuda_bf16.h>
#include <cstdint>

#define NB   2
#define NC   512
#define NN   4096
#define NUU  1024
#define NHEAD 8
#define HD   64
#define SCALE_ 0.125f

// ---------------- mma.sync helpers --------------------------------------------
__device__ __forceinline__ unsigned smem_u32(const void* p) {
    unsigned a;
    asm("{ .reg .u64 t; cvta.to.shared.u64 t, %1; cvt.u32.u64 %0, t; }" : "=r"(a) : "l"(p));
    return a;
}
#define SWZ(o) ((o) ^ (((o) >> 3) & 0x70))

#define LDMX4(r, addr) \
    asm volatile("ldmatrix.sync.aligned.m8n8.x4.shared.b16 {%0,%1,%2,%3},[%4];" \
        : "=r"((r)[0]), "=r"((r)[1]), "=r"((r)[2]), "=r"((r)[3]) : "r"(addr))

#define MMA16816(d, a, b0, b1) \
    asm volatile("mma.sync.aligned.m16n8k16.row.col.f32.bf16.bf16.f32 " \
        "{%0,%1,%2,%3},{%4,%5,%6,%7},{%8,%9},{%0,%1,%2,%3};" \
        : "+f"((d)[0]), "+f"((d)[1]), "+f"((d)[2]), "+f"((d)[3]) \
        : "r"((a)[0]), "r"((a)[1]), "r"((a)[2]), "r"((a)[3]), "r"(b0), "r"(b1))

#define CPA16(dst, src) \
    asm volatile("cp.async.cg.shared.global [%0],[%1],16;" :: "r"(dst), "l"(src))
#define CPA_COMMIT() asm volatile("cp.async.commit_group;" ::: "memory")
#define CPA_WAIT(n)  asm volatile("cp.async.wait_group %0;" :: "n"(n) : "memory")

__device__ __forceinline__ unsigned bfpack(__nv_bfloat16 a, __nv_bfloat16 b) {
    __nv_bfloat162 t(a, b); return *(unsigned*)&t;
}

// ---------------- scratch (device globals) ------------------------------------
__device__ float g_q     [NB*NHEAD*NN*HD];        // [b,h,n,d]
__device__ float g_fk    [NB*NHEAD*NN*HD];
__device__ float g_fv    [NB*NHEAD*NN*HD];
__device__ float g_k     [NB*NHEAD*NUU*HD];       // [b,h,m,d]
__device__ float g_v     [NB*NHEAD*NUU*HD];
__device__ float g_coarse[NB*NHEAD*NN*HD];
__device__ float g_xsum  [NB*NC*NN];              // x_out (+ v_pe) in [b,c,n]
__device__ float g_heat  [NB*NUU];
__device__ float g_qmean [NB*NHEAD*HD];
__device__ int   g_idxf  [NB*NHEAD*64];
// pre-split bf16 weights: rows 0..511 = q_w, 512..1535 = kv_w, 1536..2047 = proj_w
__device__ __nv_bfloat16 g_wh [2048*512], g_wl [2048*512];
// pre-split bf16 operands for flash (produced by conv epilogues)
__device__ __nv_bfloat16 g_qh [NB*NHEAD*NN*HD],  g_ql [NB*NHEAD*NN*HD];
__device__ __nv_bfloat16 g_kh [NB*NHEAD*NUU*HD], g_kl [NB*NHEAD*NUU*HD];
__device__ __nv_bfloat16 g_vth[NB*NHEAD*HD*NUU], g_vtl[NB*NHEAD*HD*NUU];

// ---------------- weight pre-split ---------------------------------------------
__global__ void split_weights(const float* __restrict__ qw, const float* __restrict__ kvw,
                              const float* __restrict__ pw)
{
    int r = blockIdx.x;
    const float* src = r < 512 ? qw + (size_t)r * 512
                     : r < 1536 ? kvw + (size_t)(r - 512) * 512
                                : pw + (size_t)(r - 1536) * 512;
    for (int c = threadIdx.x; c < 512; c += 256) {
        float v = src[c];
        __nv_bfloat16 h = __float2bfloat16(v);
        g_wh[(size_t)r * 512 + c] = h;
        g_wl[(size_t)r * 512 + c] = __float2bfloat16(v - __bfloat162float(h));
    }
}

// ---------------- conv1x1 GEMM via mma.sync bf16-split --------------------------
#define CONV_SMEM (66048 + 1024)

template<int MODE>
__global__ void __launch_bounds__(256, 2)
conv_mma(const float* __restrict__ X, int wrow,
         const float* __restrict__ bias, float* __restrict__ out, int N)
{
    extern __shared__ char smraw[];
    unsigned sb = smem_u32(smraw);
    unsigned base = (sb + 1023) & ~1023u;
    char* S = smraw + (base - sb);
    const unsigned S_WH = 0, S_WL = 16384, S_XH = 32768, S_XL = 49152;
    float* Ds = (float*)S;
    __shared__ float sbias[128];

    int tid = threadIdx.x, l = tid & 31, wid = tid >> 5;
    int warp_o = wid & 3, warp_n = wid >> 2;
    int b = blockIdx.z, otile = blockIdx.y * 128, ntile = blockIdx.x * 128;
    const float* Xb = (MODE == 2 ? g_xsum : X) + (size_t)b * 512 * N;
    const __nv_bfloat16* Wh = g_wh + (size_t)(wrow + otile) * 512;
    const __nv_bfloat16* Wl = g_wl + (size_t)(wrow + otile) * 512;

    if (tid < 128) sbias[tid] = bias[otile + tid];

    float acc[2][8][4] = {};

    unsigned a_base = (unsigned)((warp_o * 32 + (l & 15)) * 128 + (l >> 4) * 16);
    unsigned b_base = (unsigned)((warp_n * 64 + (l & 7) + ((l >> 4) << 3)) * 128
                                 + ((l >> 3) & 1) * 16);

    for (int c = 0; c < 8; c++) {
        int kk = c * 64;
#pragma unroll
        for (int it = 0; it < 4; it++) {
            int e = tid + it * 256;
            int row = e >> 3, u = e & 7;
            unsigned soff = SWZ((unsigned)(row * 128 + u * 16));
            CPA16(base + S_WH + soff, (const char*)(Wh + (size_t)row * 512 + kk) + u * 16);
            CPA16(base + S_WL + soff, (const char*)(Wl + (size_t)row * 512 + kk) + u * 16);
        }
        CPA_COMMIT();
#pragma unroll
        for (int it = 0; it < 16; it++) {
            int e = tid + it * 256;
            int n = e & 127, kp = e >> 7;
            float x0 = Xb[(size_t)(kk + 2 * kp) * N + ntile + n];
            float x1 = Xb[(size_t)(kk + 2 * kp + 1) * N + ntile + n];
            __nv_bfloat16 h0 = __float2bfloat16(x0);
            __nv_bfloat16 h1 = __float2bfloat16(x1);
            __nv_bfloat162 hp; hp.x = h0; hp.y = h1;
            __nv_bfloat162 lp;
            lp.x = __float2bfloat16(x0 - __bfloat162float(h0));
            lp.y = __float2bfloat16(x1 - __bfloat162float(h1));
            unsigned off = SWZ((unsigned)(n * 128 + kp * 4));
            *(__nv_bfloat162*)(S + S_XH + off) = hp;
            *(__nv_bfloat162*)(S + S_XL + off) = lp;
        }
        CPA_WAIT(0);
        __syncthreads();

#pragma unroll
        for (int ks = 0; ks < 4; ks++) {
            unsigned ko = ks * 32;
            unsigned ah[2][4], al[2][4];
#pragma unroll
            for (int mi = 0; mi < 2; mi++) {
                unsigned offA = SWZ(a_base + mi * 2048 + ko);
                LDMX4(ah[mi], base + S_WH + offA);
                LDMX4(al[mi], base + S_WL + offA);
            }
#pragma unroll
            for (int njp = 0; njp < 4; njp++) {
                unsigned offB = SWZ(b_base + njp * 2048 + ko);
                unsigned bh[4], bl[4];
                LDMX4(bh, base + S_XH + offB);
                LDMX4(bl, base + S_XL + offB);
#pragma unroll
                for (int mi = 0; mi < 2; mi++) {
                    MMA16816(acc[mi][njp * 2],     ah[mi], bh[0], bh[1]);
                    MMA16816(acc[mi][njp * 2],     ah[mi], bl[0], bl[1]);
                    MMA16816(acc[mi][njp * 2],     al[mi], bh[0], bh[1]);
                    MMA16816(acc[mi][njp * 2 + 1], ah[mi], bh[2], bh[3]);
                    MMA16816(acc[mi][njp * 2 + 1], ah[mi], bl[2], bl[3]);
                    MMA16816(acc[mi][njp * 2 + 1], al[mi], bh[2], bh[3]);
                }
            }
        }
        __syncthreads();
    }

    int r_base = warp_o * 32 + (l >> 2);
    int c_base = warp_n * 64 + 2 * (l & 3);
#pragma unroll
    for (int mi = 0; mi < 2; mi++)
#pragma unroll
        for (int nt = 0; nt < 8; nt++) {
            float* d0 = &Ds[(r_base + mi * 16) * 129 + c_base + nt * 8];
            d0[0]           = acc[mi][nt][0];
            d0[1]           = acc[mi][nt][1];
            d0[8 * 129]     = acc[mi][nt][2];
            d0[8 * 129 + 1] = acc[mi][nt][3];
        }
    __syncthreads();

    if (MODE == 0) {
        for (int e = tid; e < 16384; e += 256) {
            int d = e & 63, n = (e >> 6) & 127, h2 = e >> 13;
            int o = h2 * 64 + d;
            int h = (otile >> 6) + h2;
            float v = Ds[o * 129 + n] + sbias[o];
            size_t idx = ((size_t)(b * NHEAD + h) * NN + ntile + n) * HD + d;
            g_q[idx] = v;
            __nv_bfloat16 hv = __float2bfloat16(v);
            g_qh[idx] = hv;
            g_ql[idx] = __float2bfloat16(v - __bfloat162float(hv));
        }
    } else if (MODE == 1) {
        int h = otile >> 7;
        for (int e = tid; e < 16384; e += 256) {
            int d = e & 63, n = (e >> 6) & 127, half = e >> 13;
            int o = half * 64 + d;
            float* p = half ? g_fv : g_fk;
            p[((size_t)(b * NHEAD + h) * NN + ntile + n) * HD + d] = Ds[o * 129 + n] + sbias[o];
        }
    } else if (MODE == 3) {
        int h = otile >> 7;
        for (int e = tid; e < 16384; e += 256) {
            int d = e & 63, n = (e >> 6) & 127, half = e >> 13;
            int o = half * 64 + d;
            float* p = half ? g_v : g_k;
            p[((size_t)(b * NHEAD + h) * NUU + ntile + n) * HD + d] = Ds[o * 129 + n] + sbias[o];
        }
        for (int e = tid; e < 8192; e += 256) {     // K bf16 split [m][d]
            int d = e & 63, n = e >> 6;
            float v = Ds[d * 129 + n] + sbias[d];
            size_t idx = ((size_t)(b * NHEAD + h) * NUU + ntile + n) * HD + d;
            __nv_bfloat16 hv = __float2bfloat16(v);
            g_kh[idx] = hv;
            g_kl[idx] = __float2bfloat16(v - __bfloat162float(hv));
        }
        for (int e = tid; e < 8192; e += 256) {     // V^T bf16 split [d][m]
            int m = e & 127, r = e >> 7;
            float v = Ds[(64 + r) * 129 + m] + sbias[64 + r];
            size_t idx = ((size_t)(b * NHEAD + h) * HD + r) * NUU + ntile + m;
            __nv_bfloat16 hv = __float2bfloat16(v);
            g_vth[idx] = hv;
            g_vtl[idx] = __float2bfloat16(v - __bfloat162float(hv));
        }
    } else {
        for (int e = tid; e < 16384; e += 256) {
            int n = e & 127, o = e >> 7;
            out[((size_t)b * 512 + otile + o) * (size_t)NN + ntile + n] = Ds[o * 129 + n] + sbias[o];
        }
    }
}

// ---------------- flash attention: cp.async double-buffered K/V, 2 blocks/SM ---
#define FLASH_SMEM (98304 + 1024)

__global__ void __launch_bounds__(256, 2)
flash_mma()
{
    extern __shared__ char smraw[];
    unsigned sb = smem_u32(smraw);
    unsigned base = (sb + 1023) & ~1023u;
    const unsigned QH = 0, QL = 16384, KV0 = 32768;
    int tid = threadIdx.x, l = tid & 31, w = tid >> 5;
    int bh = blockIdx.y, ntile = blockIdx.x * 128;

    auto stageKV = [&](int buf, int mt) {
        unsigned bb = base + KV0 + (unsigned)buf * 32768;
        const char* kh = (const char*)(g_kh + ((size_t)bh * NUU + mt * 64) * HD);
        const char* kl = (const char*)(g_kl + ((size_t)bh * NUU + mt * 64) * HD);
#pragma unroll
        for (int it = 0; it < 2; it++) {
            int e = tid + it * 256;
            unsigned off = SWZ((unsigned)(e * 16));
            CPA16(bb + off,        kh + (size_t)e * 16);
            CPA16(bb + 8192 + off, kl + (size_t)e * 16);
        }
#pragma unroll
        for (int it = 0; it < 2; it++) {
            int e = tid + it * 256;
            int d = e >> 3, u = e & 7;
            unsigned off = SWZ((unsigned)(d * 128 + u * 16));
            CPA16(bb + 16384 + off,
                  (const char*)(g_vth + ((size_t)bh * HD + d) * NUU + mt * 64) + u * 16);
            CPA16(bb + 24576 + off,
                  (const char*)(g_vtl + ((size_t)bh * HD + d) * NUU + mt * 64) + u * 16);
        }
    };

    {
        const char* qh = (const char*)(g_qh + ((size_t)bh * NN + ntile) * HD);
        const char* ql = (const char*)(g_ql + ((size_t)bh * NN + ntile) * HD);
#pragma unroll
        for (int it = 0; it < 4; it++) {
            int e = tid + it * 256;
            unsigned off = SWZ((unsigned)(e * 16));
            CPA16(base + QH + off, qh + (size_t)e * 16);
            CPA16(base + QL + off, ql + (size_t)e * 16);
        }
        stageKV(0, 0);
        CPA_COMMIT();
    }

    float M0 = -1e30f, M1 = -1e30f, L0 = 0.f, L1 = 0.f;
    float acc[8][4] = {};
    unsigned a_base = (unsigned)((w * 16 + (l & 15)) * 128 + (l >> 4) * 16);
    unsigned b_base = (unsigned)(((l & 7) + ((l >> 4) << 3)) * 128 + ((l >> 3) & 1) * 16);

    for (int mt = 0; mt < 16; mt++) {
        if (mt < 15) { stageKV((mt + 1) & 1, mt + 1); CPA_COMMIT(); CPA_WAIT(1); }
        else CPA_WAIT(0);
        __syncthreads();
        unsigned bb = base + KV0 + (unsigned)(mt & 1) * 32768;
        const unsigned KH = bb, KL = bb + 8192, VH = bb + 16384, VL = bb + 24576;

        float s[8][4] = {};
#pragma unroll
        for (int ks = 0; ks < 4; ks++) {
            unsigned ko = ks * 32;
            unsigned aH[4], aL[4];
            LDMX4(aH, base + QH + SWZ(a_base + ko));
            LDMX4(aL, base + QL + SWZ(a_base + ko));
#pragma unroll
            for (int nj = 0; nj < 4; nj++) {
                unsigned offB = SWZ(b_base + nj * 2048 + ko);
                unsigned bH[4], bL[4];
                LDMX4(bH, KH + offB);
                LDMX4(bL, KL + offB);
                MMA16816(s[nj * 2],     aH, bH[0], bH[1]);
                MMA16816(s[nj * 2],     aH, bL[0], bL[1]);
                MMA16816(s[nj * 2],     aL, bH[0], bH[1]);
                MMA16816(s[nj * 2 + 1], aH, bH[2], bH[3]);
                MMA16816(s[nj * 2 + 1], aH, bL[2], bL[3]);
                MMA16816(s[nj * 2 + 1], aL, bH[2], bH[3]);
            }
        }

        float rm0 = -1e30f, rm1 = -1e30f;
#pragma unroll
        for (int j = 0; j < 8; j++) {
#pragma unroll
            for (int c = 0; c < 4; c++) s[j][c] *= SCALE_;
            rm0 = fmaxf(rm0, fmaxf(s[j][0], s[j][1]));
            rm1 = fmaxf(rm1, fmaxf(s[j][2], s[j][3]));
        }
        rm0 = fmaxf(rm0, __shfl_xor_sync(0xffffffffu, rm0, 1));
        rm0 = fmaxf(rm0, __shfl_xor_sync(0xffffffffu, rm0, 2));
        rm1 = fmaxf(rm1, __shfl_xor_sync(0xffffffffu, rm1, 1));
        rm1 = fmaxf(rm1, __shfl_xor_sync(0xffffffffu, rm1, 2));
        float Mn0 = fmaxf(M0, rm0), Mn1 = fmaxf(M1, rm1);
        float al0 = __expf(M0 - Mn0), al1 = __expf(M1 - Mn1);
        M0 = Mn0; M1 = Mn1;

        float rs0 = 0.f, rs1 = 0.f;
        unsigned phx[8], phy[8], plx[8], ply[8];
#pragma unroll
        for (int j = 0; j < 8; j++) {
            float p0 = __expf(s[j][0] - Mn0), p1 = __expf(s[j][1] - Mn0);
            float p2 = __expf(s[j][2] - Mn1), p3 = __expf(s[j][3] - Mn1);
            rs0 += p0 + p1; rs1 += p2 + p3;
            __nv_bfloat16 h0 = __float2bfloat16(p0), h1 = __float2bfloat16(p1);
            __nv_bfloat16 h2 = __float2bfloat16(p2), h3 = __float2bfloat16(p3);
            phx[j] = bfpack(h0, h1);
            phy[j] = bfpack(h2, h3);
            plx[j] = bfpack(__float2bfloat16(p0 - __bfloat162float(h0)),
                            __float2bfloat16(p1 - __bfloat162float(h1)));
            ply[j] = bfpack(__float2bfloat16(p2 - __bfloat162float(h2)),
                            __float2bfloat16(p3 - __bfloat162float(h3)));
        }
        rs0 += __shfl_xor_sync(0xffffffffu, rs0, 1);
        rs0 += __shfl_xor_sync(0xffffffffu, rs0, 2);
        rs1 += __shfl_xor_sync(0xffffffffu, rs1, 1);
        rs1 += __shfl_xor_sync(0xffffffffu, rs1, 2);
        L0 = L0 * al0 + rs0;
        L1 = L1 * al1 + rs1;
#pragma unroll
        for (int j = 0; j < 8; j++) {
            acc[j][0] *= al0; acc[j][1] *= al0;
            acc[j][2] *= al1; acc[j][3] *= al1;
        }

#pragma unroll
        for (int ks = 0; ks < 4; ks++) {
            unsigned aH[4] = {phx[2 * ks], phy[2 * ks], phx[2 * ks + 1], phy[2 * ks + 1]};
            unsigned aL[4] = {plx[2 * ks], ply[2 * ks], plx[2 * ks + 1], ply[2 * ks + 1]};
            unsigned ko = ks * 32;
#pragma unroll
            for (int nj = 0; nj < 4; nj++) {
                unsigned offB = SWZ(b_base + nj * 2048 + ko);
                unsigned vH[4], vL[4];
                LDMX4(vH, VH + offB);
                LDMX4(vL, VL + offB);
                MMA16816(acc[nj * 2],     aH, vH[0], vH[1]);
                MMA16816(acc[nj * 2],     aH, vL[0], vL[1]);
                MMA16816(acc[nj * 2],     aL, vH[0], vH[1]);
                MMA16816(acc[nj * 2 + 1], aH, vH[2], vH[3]);
                MMA16816(acc[nj * 2 + 1], aH, vL[2], vL[3]);
                MMA16816(acc[nj * 2 + 1], aL, vH[2], vH[3]);
            }
        }
        __syncthreads();
    }

    float inv0 = 1.f / L0, inv1 = 1.f / L1;
    int r0 = ntile + w * 16 + (l >> 2);
    float* C0 = &g_coarse[((size_t)bh * NN + r0) * HD];
    float* C1 = C0 + 8 * HD;
#pragma unroll
    for (int j = 0; j < 8; j++) {
        int col = j * 8 + (l & 3) * 2;
        *(float2*)&C0[col] = make_float2(acc[j][0] * inv0, acc[j][1] * inv0);
        *(float2*)&C1[col] = make_float2(acc[j][2] * inv1, acc[j][3] * inv1);
    }
}

// ---------------- heat: coalesced, one block per (b, hu) -----------------------
__global__ void heat_kernel(const float* __restrict__ x)
{
    int bi = blockIdx.x;
    int b = bi >> 5, hu = bi & 31;
    int t = threadIdx.x;
    int g = t >> 6, j = t & 63;
    int r = j >> 5, wu = j & 31;
    const float* xp = x + (size_t)b * NC * NN + (size_t)(2 * hu + r) * 64 + 2 * wu;
    float s = 0.f;
#pragma unroll 4
    for (int c = g * 32; c < g * 32 + 32; c++) {
        float2 v = *(const float2*)(xp + (size_t)c * NN);
        s += v.x + v.y;
    }
    __shared__ float red[1024];
    red[t] = s;
    __syncthreads();
    if (t < 32) {
        float a = 0.f;
#pragma unroll
        for (int gg = 0; gg < 16; gg++)
            a += red[gg * 64 + t] + red[gg * 64 + 32 + t];
        g_heat[b * NUU + hu * 32 + t] = a * (1.f / 2048.f);
    }
}

// ---------------- qmean (1024 threads) ------------------------------------------
__global__ void qmean_kernel()
{
    int bh = blockIdx.x;
    int t = threadIdx.x;
    int d = t & 63, seg = t >> 6;
    float s = 0.f;
    const float* Q = g_q + (size_t)bh * NN * HD;
    for (int n = seg * 256; n < seg * 256 + 256; n++) s += Q[(size_t)n * HD + d];
    __shared__ float red[1024];
    red[t] = s; __syncthreads();
    if (seg == 0) {
        float a = 0.f;
#pragma unroll
        for (int i = 0; i < 16; i++) a += red[i * 64 + d];
        g_qmean[bh * HD + d] = a * (1.f / (float)NN);
    }
}

// ---------------- topk ---------------------------------------------------------
__global__ void topk_kernel(const float* __restrict__ gumbel)
{
    int bh = blockIdx.x;
    int b = bh >> 3;
    int t = threadIdx.x;
    __shared__ float s[NUU];
    __shared__ float qm[HD];
    __shared__ float rv[256];
    __shared__ int   ri[256];
    if (t < HD) qm[t] = g_qmean[bh * HD + t];
    __syncthreads();
    for (int m = t; m < NUU; m += 256) {
        const float* kp = g_k + ((size_t)bh * NUU + m) * HD;
        float dot = 0.f;
#pragma unroll
        for (int d = 0; d < HD; d++) dot += qm[d] * kp[d];
        s[m] = dot * SCALE_ * g_heat[b * NUU + m] + gumbel[(size_t)bh * NUU + m];
    }
    __syncthreads();
    for (int it = 0; it < 16; it++) {
        float bv = -1e30f; int bi = 0x7fffffff;
        for (int m = t; m < NUU; m += 256) {
            float v = s[m];
            if (v > bv || (v == bv && m < bi)) { bv = v; bi = m; }
        }
        rv[t] = bv; ri[t] = bi; __syncthreads();
        for (int off = 128; off; off >>= 1) {
            if (t < off) {
                float v2 = rv[t + off]; int i2 = ri[t + off];
                if (v2 > rv[t] || (v2 == rv[t] && i2 < ri[t])) { rv[t] = v2; ri[t] = i2; }
            }
            __syncthreads();
        }
        if (t == 0) {
            int m = ri[0];
            s[m] = -1e38f;
            int hi = (m >> 5) * 2, wi = (m & 31) * 2;
            int base = hi * 64 + wi;
            g_idxf[bh * 64 +       it] = base;
            g_idxf[bh * 64 + 16 +  it] = base + 1;
            g_idxf[bh * 64 + 32 +  it] = base + 64;
            g_idxf[bh * 64 + 48 +  it] = base + 65;
        }
        __syncthreads();
    }
}

// ---------------- fine attention + gate + blend ----------------------------------
struct FineSmem {
    float Ks[64][65];
    float Vs[64][64];
    float Gw[128][64];
    float Os[64][65];
    int   idx[64];
    float gb[64];
};

__global__ void __launch_bounds__(256, 2)
fine_kernel(const float* __restrict__ gate_w, const float* __restrict__ gate_b)
{
    extern __shared__ char smem_raw[];
    FineSmem* S = reinterpret_cast<FineSmem*>(smem_raw);
    int bh = blockIdx.y;
    int b = bh >> 3, h = bh & 7;
    int ntile = blockIdx.x * 64;
    int t = threadIdx.x;

    if (t < 64) { S->idx[t] = g_idxf[bh * 64 + t]; S->gb[t] = gate_b[t]; }
    for (int e = t; e < 8192; e += 256) {
        int o = e >> 7, c = e & 127;
        S->Gw[c][o] = gate_w[e];
    }
    __syncthreads();
    for (int e = t; e < 4096; e += 256) {
        int m = e >> 6, d = e & 63;
        size_t src = ((size_t)bh * NN + S->idx[m]) * HD + d;
        S->Ks[m][d] = g_fk[src];
        S->Vs[m][d] = g_fv[src];
    }
    __syncthreads();

    int w = t >> 5, l = t & 31;
    for (int qi = 0; qi < 8; qi++) {
        int n = ntile + w * 8 + qi;
        const float* qp = g_q + ((size_t)bh * NN + n) * HD;
        float q0 = qp[l], q1 = qp[l + 32];
        float s0 = 0.f, s1 = 0.f;
#pragma unroll
        for (int d = 0; d < 64; d++) {
            float qd = __shfl_sync(0xffffffffu, d < 32 ? q0 : q1, d & 31);
            s0 += qd * S->Ks[l][d];
            s1 += qd * S->Ks[l + 32][d];
        }
        s0 *= SCALE_; s1 *= SCALE_;
        float mx = fmaxf(s0, s1);
#pragma unroll
        for (int off = 16; off; off >>= 1) mx = fmaxf(mx, __shfl_xor_sync(0xffffffffu, mx, off));
        float p0 = __expf(s0 - mx), p1 = __expf(s1 - mx);
        float sm = p0 + p1;
#pragma unroll
        for (int off = 16; off; off >>= 1) sm += __shfl_xor_sync(0xffffffffu, sm, off);
        float inv = 1.f / sm;
        p0 *= inv; p1 *= inv;

        float r0 = 0.f, r1 = 0.f;
#pragma unroll
        for (int m = 0; m < 64; m++) {
            float pm = __shfl_sync(0xffffffffu, m < 32 ? p0 : p1, m & 31);
            r0 += pm * S->Vs[m][l];
            r1 += pm * S->Vs[m][l + 32];
        }
        const float* cp = g_coarse + ((size_t)bh * NN + n) * HD;
        float c0 = cp[l], c1 = cp[l + 32];

        float g0 = S->gb[l], g1 = S->gb[l + 32];
#pragma unroll
        for (int c = 0; c < 64; c++) {
            float cv = __shfl_sync(0xffffffffu, c < 32 ? c0 : c1, c & 31);
            g0 += cv * S->Gw[c][l];
            g1 += cv * S->Gw[c][l + 32];
        }
#pragma unroll
        for (int c = 0; c < 64; c++) {
            float rvv = __shfl_sync(0xffffffffu, c < 32 ? r0 : r1, c & 31);
            g0 += rvv * S->Gw[64 + c][l];
            g1 += rvv * S->Gw[64 + c][l + 32];
        }
        g0 = 1.f / (1.f + __expf(-g0));
        g1 = 1.f / (1.f + __expf(-g1));
        int nl = w * 8 + qi;
        S->Os[l][nl]      = g0 * r0 + (1.f - g0) * c0;
        S->Os[l + 32][nl] = g1 * r1 + (1.f - g1) * c1;
    }
    __syncthreads();
    for (int e = t; e < 4096; e += 256) {
        int d = e >> 6, nl = e & 63;
        g_xsum[((size_t)b * NC + h * 64 + d) * NN + ntile + nl] = S->Os[d][nl];
    }
}

// ---------------- fused depthwise 7x7 conv + bilinear upsample-add -------------
__global__ void pe_bilinear(const float* __restrict__ pe_w, const float* __restrict__ pe_b)
{
    int bc = blockIdx.x;
    int b = bc >> 9, c = bc & 511;
    int h = c >> 6, d = c & 63;
    __shared__ float img[1024];
    __shared__ float pet[1024];
    __shared__ float wt[49];
    int t = threadIdx.x;
    for (int p = t; p < 1024; p += 256)
        img[p] = g_v[((size_t)(b * NHEAD + h) * NUU + p) * HD + d];
    if (t < 49) wt[t] = pe_w[c * 49 + t];
    __syncthreads();
    float bias = pe_b[c];
    for (int p = t; p < 1024; p += 256) {
        int y = p >> 5, xx0 = p & 31;
        float s = bias;
#pragma unroll
        for (int ky = 0; ky < 7; ky++) {
            int yy = y + ky - 3;
            if (yy < 0 || yy > 31) continue;
#pragma unroll
            for (int kx = 0; kx < 7; kx++) {
                int xx = xx0 + kx - 3;
                if (xx < 0 || xx > 31) continue;
                s += wt[ky * 7 + kx] * img[yy * 32 + xx];
            }
        }
        pet[p] = s;
    }
    __syncthreads();
    for (int p = t; p < 4096; p += 256) {
        int i = p >> 6, j = p & 63;
        int ti = i >> 1, tj = j >> 1;
        int y0, y1, x0, x1; float wy0, wy1, wx0, wx1;
        if (i & 1) { y0 = ti; y1 = min(ti + 1, 31); wy0 = 0.75f; wy1 = 0.25f; }
        else       { y0 = max(ti - 1, 0); y1 = ti;  wy0 = 0.25f; wy1 = 0.75f; }
        if (j & 1) { x0 = tj; x1 = min(tj + 1, 31); wx0 = 0.75f; wx1 = 0.25f; }
        else       { x0 = max(tj - 1, 0); x1 = tj;  wx0 = 0.25f; wx1 = 0.75f; }
        float v = wy0 * (wx0 * pet[y0 * 32 + x0] + wx1 * pet[y0 * 32 + x1])
                + wy1 * (wx0 * pet[y1 * 32 + x0] + wx1 * pet[y1 * 32 + x1]);
        g_xsum[(size_t)bc * 4096 + p] += v;
    }
}

// ---------------- launch: stream-forked DAG --------------------------------------
extern "C" void kernel_launch(void* const* d_in, const int* in_sizes, int n_in,
                              void* d_out, int out_size)
{
    const float* x      = (const float*)d_in[0];
    const float* upper  = (const float*)d_in[1];
    const float* gumbel = (const float*)d_in[2];
    const float* q_w    = (const float*)d_in[3];
    const float* q_b    = (const float*)d_in[4];
    const float* kv_w   = (const float*)d_in[5];
    const float* kv_b   = (const float*)d_in[6];
    const float* proj_w = (const float*)d_in[7];
    const float* proj_b = (const float*)d_in[8];
    const float* pe_w   = (const float*)d_in[9];
    const float* pe_b   = (const float*)d_in[10];
    const float* gate_w = (const float*)d_in[11];
    const float* gate_b = (const float*)d_in[12];
    float* out = (float*)d_out;

    cudaFuncSetAttribute(fine_kernel, cudaFuncAttributeMaxDynamicSharedMemorySize,
                         (int)sizeof(FineSmem));
    cudaFuncSetAttribute(flash_mma, cudaFuncAttributeMaxDynamicSharedMemorySize, FLASH_SMEM);
    cudaFuncSetAttribute(conv_mma<0>, cudaFuncAttributeMaxDynamicSharedMemorySize, CONV_SMEM);
    cudaFuncSetAttribute(conv_mma<1>, cudaFuncAttributeMaxDynamicSharedMemorySize, CONV_SMEM);
    cudaFuncSetAttribute(conv_mma<2>, cudaFuncAttributeMaxDynamicSharedMemorySize, CONV_SMEM);
    cudaFuncSetAttribute(conv_mma<3>, cudaFuncAttributeMaxDynamicSharedMemorySize, CONV_SMEM);

    dim3 blk(256);

    cudaStream_t s1, s2;
    cudaStreamCreateWithFlags(&s1, cudaStreamNonBlocking);
    cudaStreamCreateWithFlags(&s2, cudaStreamNonBlocking);
    cudaEvent_t ev_sw, ev_c0, ev_c3, ev_c1, ev_t;
    cudaEventCreateWithFlags(&ev_sw, cudaEventDisableTiming);
    cudaEventCreateWithFlags(&ev_c0, cudaEventDisableTiming);
    cudaEventCreateWithFlags(&ev_c3, cudaEventDisableTiming);
    cudaEventCreateWithFlags(&ev_c1, cudaEventDisableTiming);
    cudaEventCreateWithFlags(&ev_t,  cudaEventDisableTiming);

    // ---- main stream: weights -> conv0 -> conv3 -> flash ----
    split_weights<<<2048, blk>>>(q_w, kv_w, proj_w);
    cudaEventRecord(ev_sw, 0);
    conv_mma<0><<<dim3(NN / 128,  512 / 128, NB), blk, CONV_SMEM>>>(x, 0, q_b, nullptr, NN);
    cudaEventRecord(ev_c0, 0);
    conv_mma<3><<<dim3(NUU / 128, 1024 / 128, NB), blk, CONV_SMEM>>>(upper, 512, kv_b, nullptr, NUU);
    cudaEventRecord(ev_c3, 0);

    // ---- s1: conv1 (independent of flash) ----
    cudaStreamWaitEvent(s1, ev_sw, 0);
    conv_mma<1><<<dim3(NN / 128, 1024 / 128, NB), blk, CONV_SMEM, s1>>>(x, 512, kv_b, nullptr, NN);
    cudaEventRecord(ev_c1, s1);

    // ---- s2: heat -> qmean -> topk (independent of flash) ----
    cudaStreamWaitEvent(s2, ev_sw, 0);
    heat_kernel<<<NB * 32, 1024, 0, s2>>>(x);
    cudaStreamWaitEvent(s2, ev_c0, 0);
    qmean_kernel<<<NB * NHEAD, 1024, 0, s2>>>();
    cudaStreamWaitEvent(s2, ev_c3, 0);
    topk_kernel<<<NB * NHEAD, blk, 0, s2>>>(gumbel);
    cudaEventRecord(ev_t, s2);

    // ---- main stream: flash runs concurrently with s1/s2 ----
    flash_mma<<<dim3(NN / 128, NB * NHEAD), blk, FLASH_SMEM>>>();

    // ---- join, then tail ----
    cudaStreamWaitEvent(0, ev_c1, 0);
    cudaStreamWaitEvent(0, ev_t, 0);

    fine_kernel<<<dim3(NN / 64, NB * NHEAD), blk, sizeof(FineSmem)>>>(gate_w, gate_b);
    pe_bilinear<<<NB * NC, blk>>>(pe_w, pe_b);
    conv_mma<2><<<dim3(NN / 128, 512 / 128, NB), blk, CONV_SMEM>>>(nullptr, 1536, proj_b, out, NN);

    cudaEventDestroy(ev_sw);
    cudaEventDestroy(ev_c0);
    cudaEventDestroy(ev_c3);
    cudaEventDestroy(ev_c1);
    cudaEventDestroy(ev_t);
    cudaStreamDestroy(s1);
    cudaStreamDestroy(s2);
}

// round 17
// speedup vs baseline: 1.2549x; 1.0032x over previous
#include <cuda_runtime.h>
#include <cuda_bf16.h>
#include <cstdint>

#define NB   2
#define NC   512
#define NN   4096
#define NUU  1024
#define NHEAD 8
#define HD   64
#define SCALE_ 0.125f

// ---------------- mma.sync helpers --------------------------------------------
__device__ __forceinline__ unsigned smem_u32(const void* p) {
    unsigned a;
    asm("{ .reg .u64 t; cvta.to.shared.u64 t, %1; cvt.u32.u64 %0, t; }" : "=r"(a) : "l"(p));
    return a;
}
#define SWZ(o) ((o) ^ (((o) >> 3) & 0x70))

#define LDMX4(r, addr) \
    asm volatile("ldmatrix.sync.aligned.m8n8.x4.shared.b16 {%0,%1,%2,%3},[%4];" \
        : "=r"((r)[0]), "=r"((r)[1]), "=r"((r)[2]), "=r"((r)[3]) : "r"(addr))

#define MMA16816(d, a, b0, b1) \
    asm volatile("mma.sync.aligned.m16n8k16.row.col.f32.bf16.bf16.f32 " \
        "{%0,%1,%2,%3},{%4,%5,%6,%7},{%8,%9},{%0,%1,%2,%3};" \
        : "+f"((d)[0]), "+f"((d)[1]), "+f"((d)[2]), "+f"((d)[3]) \
        : "r"((a)[0]), "r"((a)[1]), "r"((a)[2]), "r"((a)[3]), "r"(b0), "r"(b1))

#define CPA16(dst, src) \
    asm volatile("cp.async.cg.shared.global [%0],[%1],16;" :: "r"(dst), "l"(src))
#define CPA_COMMIT() asm volatile("cp.async.commit_group;" ::: "memory")
#define CPA_WAIT(n)  asm volatile("cp.async.wait_group %0;" :: "n"(n) : "memory")

__device__ __forceinline__ unsigned bfpack(__nv_bfloat16 a, __nv_bfloat16 b) {
    __nv_bfloat162 t(a, b); return *(unsigned*)&t;
}

// ---------------- scratch (device globals) ------------------------------------
__device__ float g_q     [NB*NHEAD*NN*HD];        // [b,h,n,d]
__device__ float g_fk    [NB*NHEAD*NN*HD];
__device__ float g_fv    [NB*NHEAD*NN*HD];
__device__ float g_k     [NB*NHEAD*NUU*HD];       // [b,h,m,d]
__device__ float g_v     [NB*NHEAD*NUU*HD];
__device__ float g_coarse[NB*NHEAD*NN*HD];
__device__ float g_xsum  [NB*NC*NN];              // x_out in [b,c,n]
__device__ float g_pe    [NB*NC*NN];              // upsampled v_pe in [b,c,n]
__device__ float g_heat  [NB*NUU];
__device__ float g_qmean [NB*NHEAD*HD];
__device__ int   g_idxf  [NB*NHEAD*64];
// pre-split bf16 weights: rows 0..511 = q_w, 512..1535 = kv_w, 1536..2047 = proj_w
__device__ __nv_bfloat16 g_wh [2048*512], g_wl [2048*512];
// pre-split bf16 operands for flash (produced by conv epilogues)
__device__ __nv_bfloat16 g_qh [NB*NHEAD*NN*HD],  g_ql [NB*NHEAD*NN*HD];
__device__ __nv_bfloat16 g_kh [NB*NHEAD*NUU*HD], g_kl [NB*NHEAD*NUU*HD];
__device__ __nv_bfloat16 g_vth[NB*NHEAD*HD*NUU], g_vtl[NB*NHEAD*HD*NUU];

// ---------------- weight pre-split ---------------------------------------------
__global__ void split_weights(const float* __restrict__ qw, const float* __restrict__ kvw,
                              const float* __restrict__ pw)
{
    int r = blockIdx.x;
    const float* src = r < 512 ? qw + (size_t)r * 512
                     : r < 1536 ? kvw + (size_t)(r - 512) * 512
                                : pw + (size_t)(r - 1536) * 512;
    for (int c = threadIdx.x; c < 512; c += 256) {
        float v = src[c];
        __nv_bfloat16 h = __float2bfloat16(v);
        g_wh[(size_t)r * 512 + c] = h;
        g_wl[(size_t)r * 512 + c] = __float2bfloat16(v - __bfloat162float(h));
    }
}

// ---------------- conv1x1 GEMM via mma.sync bf16-split --------------------------
#define CONV_SMEM (66048 + 1024)

template<int MODE>
__global__ void __launch_bounds__(256, 2)
conv_mma(const float* __restrict__ X, int wrow,
         const float* __restrict__ bias, float* __restrict__ out, int N)
{
    extern __shared__ char smraw[];
    unsigned sb = smem_u32(smraw);
    unsigned base = (sb + 1023) & ~1023u;
    char* S = smraw + (base - sb);
    const unsigned S_WH = 0, S_WL = 16384, S_XH = 32768, S_XL = 49152;
    float* Ds = (float*)S;
    __shared__ float sbias[128];

    int tid = threadIdx.x, l = tid & 31, wid = tid >> 5;
    int warp_o = wid & 3, warp_n = wid >> 2;
    int b = blockIdx.z, otile = blockIdx.y * 128, ntile = blockIdx.x * 128;
    const float* Xb = (MODE == 2 ? g_xsum : X) + (size_t)b * 512 * N;
    const float* Pb = g_pe + (size_t)b * 512 * N;   // used in MODE 2 only
    const __nv_bfloat16* Wh = g_wh + (size_t)(wrow + otile) * 512;
    const __nv_bfloat16* Wl = g_wl + (size_t)(wrow + otile) * 512;

    if (tid < 128) sbias[tid] = bias[otile + tid];

    float acc[2][8][4] = {};

    unsigned a_base = (unsigned)((warp_o * 32 + (l & 15)) * 128 + (l >> 4) * 16);
    unsigned b_base = (unsigned)((warp_n * 64 + (l & 7) + ((l >> 4) << 3)) * 128
                                 + ((l >> 3) & 1) * 16);

    for (int c = 0; c < 8; c++) {
        int kk = c * 64;
#pragma unroll
        for (int it = 0; it < 4; it++) {
            int e = tid + it * 256;
            int row = e >> 3, u = e & 7;
            unsigned soff = SWZ((unsigned)(row * 128 + u * 16));
            CPA16(base + S_WH + soff, (const char*)(Wh + (size_t)row * 512 + kk) + u * 16);
            CPA16(base + S_WL + soff, (const char*)(Wl + (size_t)row * 512 + kk) + u * 16);
        }
        CPA_COMMIT();
#pragma unroll
        for (int it = 0; it < 16; it++) {
            int e = tid + it * 256;
            int n = e & 127, kp = e >> 7;
            size_t i0 = (size_t)(kk + 2 * kp) * N + ntile + n;
            size_t i1 = i0 + N;
            float x0 = Xb[i0];
            float x1 = Xb[i1];
            if (MODE == 2) { x0 += Pb[i0]; x1 += Pb[i1]; }
            __nv_bfloat16 h0 = __float2bfloat16(x0);
            __nv_bfloat16 h1 = __float2bfloat16(x1);
            __nv_bfloat162 hp; hp.x = h0; hp.y = h1;
            __nv_bfloat162 lp;
            lp.x = __float2bfloat16(x0 - __bfloat162float(h0));
            lp.y = __float2bfloat16(x1 - __bfloat162float(h1));
            unsigned off = SWZ((unsigned)(n * 128 + kp * 4));
            *(__nv_bfloat162*)(S + S_XH + off) = hp;
            *(__nv_bfloat162*)(S + S_XL + off) = lp;
        }
        CPA_WAIT(0);
        __syncthreads();

#pragma unroll
        for (int ks = 0; ks < 4; ks++) {
            unsigned ko = ks * 32;
            unsigned ah[2][4], al[2][4];
#pragma unroll
            for (int mi = 0; mi < 2; mi++) {
                unsigned offA = SWZ(a_base + mi * 2048 + ko);
                LDMX4(ah[mi], base + S_WH + offA);
                LDMX4(al[mi], base + S_WL + offA);
            }
#pragma unroll
            for (int njp = 0; njp < 4; njp++) {
                unsigned offB = SWZ(b_base + njp * 2048 + ko);
                unsigned bh[4], bl[4];
                LDMX4(bh, base + S_XH + offB);
                LDMX4(bl, base + S_XL + offB);
#pragma unroll
                for (int mi = 0; mi < 2; mi++) {
                    MMA16816(acc[mi][njp * 2],     ah[mi], bh[0], bh[1]);
                    MMA16816(acc[mi][njp * 2],     ah[mi], bl[0], bl[1]);
                    MMA16816(acc[mi][njp * 2],     al[mi], bh[0], bh[1]);
                    MMA16816(acc[mi][njp * 2 + 1], ah[mi], bh[2], bh[3]);
                    MMA16816(acc[mi][njp * 2 + 1], ah[mi], bl[2], bl[3]);
                    MMA16816(acc[mi][njp * 2 + 1], al[mi], bh[2], bh[3]);
                }
            }
        }
        __syncthreads();
    }

    int r_base = warp_o * 32 + (l >> 2);
    int c_base = warp_n * 64 + 2 * (l & 3);
#pragma unroll
    for (int mi = 0; mi < 2; mi++)
#pragma unroll
        for (int nt = 0; nt < 8; nt++) {
            float* d0 = &Ds[(r_base + mi * 16) * 129 + c_base + nt * 8];
            d0[0]           = acc[mi][nt][0];
            d0[1]           = acc[mi][nt][1];
            d0[8 * 129]     = acc[mi][nt][2];
            d0[8 * 129 + 1] = acc[mi][nt][3];
        }
    __syncthreads();

    if (MODE == 0) {
        for (int e = tid; e < 16384; e += 256) {
            int d = e & 63, n = (e >> 6) & 127, h2 = e >> 13;
            int o = h2 * 64 + d;
            int h = (otile >> 6) + h2;
            float v = Ds[o * 129 + n] + sbias[o];
            size_t idx = ((size_t)(b * NHEAD + h) * NN + ntile + n) * HD + d;
            g_q[idx] = v;
            __nv_bfloat16 hv = __float2bfloat16(v);
            g_qh[idx] = hv;
            g_ql[idx] = __float2bfloat16(v - __bfloat162float(hv));
        }
    } else if (MODE == 1) {
        int h = otile >> 7;
        for (int e = tid; e < 16384; e += 256) {
            int d = e & 63, n = (e >> 6) & 127, half = e >> 13;
            int o = half * 64 + d;
            float* p = half ? g_fv : g_fk;
            p[((size_t)(b * NHEAD + h) * NN + ntile + n) * HD + d] = Ds[o * 129 + n] + sbias[o];
        }
    } else if (MODE == 3) {
        int h = otile >> 7;
        for (int e = tid; e < 16384; e += 256) {
            int d = e & 63, n = (e >> 6) & 127, half = e >> 13;
            int o = half * 64 + d;
            float* p = half ? g_v : g_k;
            p[((size_t)(b * NHEAD + h) * NUU + ntile + n) * HD + d] = Ds[o * 129 + n] + sbias[o];
        }
        for (int e = tid; e < 8192; e += 256) {     // K bf16 split [m][d]
            int d = e & 63, n = e >> 6;
            float v = Ds[d * 129 + n] + sbias[d];
            size_t idx = ((size_t)(b * NHEAD + h) * NUU + ntile + n) * HD + d;
            __nv_bfloat16 hv = __float2bfloat16(v);
            g_kh[idx] = hv;
            g_kl[idx] = __float2bfloat16(v - __bfloat162float(hv));
        }
        for (int e = tid; e < 8192; e += 256) {     // V^T bf16 split [d][m]
            int m = e & 127, r = e >> 7;
            float v = Ds[(64 + r) * 129 + m] + sbias[64 + r];
            size_t idx = ((size_t)(b * NHEAD + h) * HD + r) * NUU + ntile + m;
            __nv_bfloat16 hv = __float2bfloat16(v);
            g_vth[idx] = hv;
            g_vtl[idx] = __float2bfloat16(v - __bfloat162float(hv));
        }
    } else {
        for (int e = tid; e < 16384; e += 256) {
            int n = e & 127, o = e >> 7;
            out[((size_t)b * 512 + otile + o) * (size_t)NN + ntile + n] = Ds[o * 129 + n] + sbias[o];
        }
    }
}

// ---------------- flash attention: cp.async double-buffered K/V, 2 blocks/SM ---
#define FLASH_SMEM (98304 + 1024)

__global__ void __launch_bounds__(256, 2)
flash_mma()
{
    extern __shared__ char smraw[];
    unsigned sb = smem_u32(smraw);
    unsigned base = (sb + 1023) & ~1023u;
    const unsigned QH = 0, QL = 16384, KV0 = 32768;
    int tid = threadIdx.x, l = tid & 31, w = tid >> 5;
    int bh = blockIdx.y, ntile = blockIdx.x * 128;

    auto stageKV = [&](int buf, int mt) {
        unsigned bb = base + KV0 + (unsigned)buf * 32768;
        const char* kh = (const char*)(g_kh + ((size_t)bh * NUU + mt * 64) * HD);
        const char* kl = (const char*)(g_kl + ((size_t)bh * NUU + mt * 64) * HD);
#pragma unroll
        for (int it = 0; it < 2; it++) {
            int e = tid + it * 256;
            unsigned off = SWZ((unsigned)(e * 16));
            CPA16(bb + off,        kh + (size_t)e * 16);
            CPA16(bb + 8192 + off, kl + (size_t)e * 16);
        }
#pragma unroll
        for (int it = 0; it < 2; it++) {
            int e = tid + it * 256;
            int d = e >> 3, u = e & 7;
            unsigned off = SWZ((unsigned)(d * 128 + u * 16));
            CPA16(bb + 16384 + off,
                  (const char*)(g_vth + ((size_t)bh * HD + d) * NUU + mt * 64) + u * 16);
            CPA16(bb + 24576 + off,
                  (const char*)(g_vtl + ((size_t)bh * HD + d) * NUU + mt * 64) + u * 16);
        }
    };

    {
        const char* qh = (const char*)(g_qh + ((size_t)bh * NN + ntile) * HD);
        const char* ql = (const char*)(g_ql + ((size_t)bh * NN + ntile) * HD);
#pragma unroll
        for (int it = 0; it < 4; it++) {
            int e = tid + it * 256;
            unsigned off = SWZ((unsigned)(e * 16));
            CPA16(base + QH + off, qh + (size_t)e * 16);
            CPA16(base + QL + off, ql + (size_t)e * 16);
        }
        stageKV(0, 0);
        CPA_COMMIT();
    }

    float M0 = -1e30f, M1 = -1e30f, L0 = 0.f, L1 = 0.f;
    float acc[8][4] = {};
    unsigned a_base = (unsigned)((w * 16 + (l & 15)) * 128 + (l >> 4) * 16);
    unsigned b_base = (unsigned)(((l & 7) + ((l >> 4) << 3)) * 128 + ((l >> 3) & 1) * 16);

    for (int mt = 0; mt < 16; mt++) {
        if (mt < 15) { stageKV((mt + 1) & 1, mt + 1); CPA_COMMIT(); CPA_WAIT(1); }
        else CPA_WAIT(0);
        __syncthreads();
        unsigned bb = base + KV0 + (unsigned)(mt & 1) * 32768;
        const unsigned KH = bb, KL = bb + 8192, VH = bb + 16384, VL = bb + 24576;

        float s[8][4] = {};
#pragma unroll
        for (int ks = 0; ks < 4; ks++) {
            unsigned ko = ks * 32;
            unsigned aH[4], aL[4];
            LDMX4(aH, base + QH + SWZ(a_base + ko));
            LDMX4(aL, base + QL + SWZ(a_base + ko));
#pragma unroll
            for (int nj = 0; nj < 4; nj++) {
                unsigned offB = SWZ(b_base + nj * 2048 + ko);
                unsigned bH[4], bL[4];
                LDMX4(bH, KH + offB);
                LDMX4(bL, KL + offB);
                MMA16816(s[nj * 2],     aH, bH[0], bH[1]);
                MMA16816(s[nj * 2],     aH, bL[0], bL[1]);
                MMA16816(s[nj * 2],     aL, bH[0], bH[1]);
                MMA16816(s[nj * 2 + 1], aH, bH[2], bH[3]);
                MMA16816(s[nj * 2 + 1], aH, bL[2], bL[3]);
                MMA16816(s[nj * 2 + 1], aL, bH[2], bH[3]);
            }
        }

        float rm0 = -1e30f, rm1 = -1e30f;
#pragma unroll
        for (int j = 0; j < 8; j++) {
#pragma unroll
            for (int c = 0; c < 4; c++) s[j][c] *= SCALE_;
            rm0 = fmaxf(rm0, fmaxf(s[j][0], s[j][1]));
            rm1 = fmaxf(rm1, fmaxf(s[j][2], s[j][3]));
        }
        rm0 = fmaxf(rm0, __shfl_xor_sync(0xffffffffu, rm0, 1));
        rm0 = fmaxf(rm0, __shfl_xor_sync(0xffffffffu, rm0, 2));
        rm1 = fmaxf(rm1, __shfl_xor_sync(0xffffffffu, rm1, 1));
        rm1 = fmaxf(rm1, __shfl_xor_sync(0xffffffffu, rm1, 2));
        float Mn0 = fmaxf(M0, rm0), Mn1 = fmaxf(M1, rm1);
        float al0 = __expf(M0 - Mn0), al1 = __expf(M1 - Mn1);
        M0 = Mn0; M1 = Mn1;

        float rs0 = 0.f, rs1 = 0.f;
        unsigned phx[8], phy[8], plx[8], ply[8];
#pragma unroll
        for (int j = 0; j < 8; j++) {
            float p0 = __expf(s[j][0] - Mn0), p1 = __expf(s[j][1] - Mn0);
            float p2 = __expf(s[j][2] - Mn1), p3 = __expf(s[j][3] - Mn1);
            rs0 += p0 + p1; rs1 += p2 + p3;
            __nv_bfloat16 h0 = __float2bfloat16(p0), h1 = __float2bfloat16(p1);
            __nv_bfloat16 h2 = __float2bfloat16(p2), h3 = __float2bfloat16(p3);
            phx[j] = bfpack(h0, h1);
            phy[j] = bfpack(h2, h3);
            plx[j] = bfpack(__float2bfloat16(p0 - __bfloat162float(h0)),
                            __float2bfloat16(p1 - __bfloat162float(h1)));
            ply[j] = bfpack(__float2bfloat16(p2 - __bfloat162float(h2)),
                            __float2bfloat16(p3 - __bfloat162float(h3)));
        }
        rs0 += __shfl_xor_sync(0xffffffffu, rs0, 1);
        rs0 += __shfl_xor_sync(0xffffffffu, rs0, 2);
        rs1 += __shfl_xor_sync(0xffffffffu, rs1, 1);
        rs1 += __shfl_xor_sync(0xffffffffu, rs1, 2);
        L0 = L0 * al0 + rs0;
        L1 = L1 * al1 + rs1;
#pragma unroll
        for (int j = 0; j < 8; j++) {
            acc[j][0] *= al0; acc[j][1] *= al0;
            acc[j][2] *= al1; acc[j][3] *= al1;
        }

#pragma unroll
        for (int ks = 0; ks < 4; ks++) {
            unsigned aH[4] = {phx[2 * ks], phy[2 * ks], phx[2 * ks + 1], phy[2 * ks + 1]};
            unsigned aL[4] = {plx[2 * ks], ply[2 * ks], plx[2 * ks + 1], ply[2 * ks + 1]};
            unsigned ko = ks * 32;
#pragma unroll
            for (int nj = 0; nj < 4; nj++) {
                unsigned offB = SWZ(b_base + nj * 2048 + ko);
                unsigned vH[4], vL[4];
                LDMX4(vH, VH + offB);
                LDMX4(vL, VL + offB);
                MMA16816(acc[nj * 2],     aH, vH[0], vH[1]);
                MMA16816(acc[nj * 2],     aH, vL[0], vL[1]);
                MMA16816(acc[nj * 2],     aL, vH[0], vH[1]);
                MMA16816(acc[nj * 2 + 1], aH, vH[2], vH[3]);
                MMA16816(acc[nj * 2 + 1], aH, vL[2], vL[3]);
                MMA16816(acc[nj * 2 + 1], aL, vH[2], vH[3]);
            }
        }
        __syncthreads();
    }

    float inv0 = 1.f / L0, inv1 = 1.f / L1;
    int r0 = ntile + w * 16 + (l >> 2);
    float* C0 = &g_coarse[((size_t)bh * NN + r0) * HD];
    float* C1 = C0 + 8 * HD;
#pragma unroll
    for (int j = 0; j < 8; j++) {
        int col = j * 8 + (l & 3) * 2;
        *(float2*)&C0[col] = make_float2(acc[j][0] * inv0, acc[j][1] * inv0);
        *(float2*)&C1[col] = make_float2(acc[j][2] * inv1, acc[j][3] * inv1);
    }
}

// ---------------- heat: coalesced, one block per (b, hu) -----------------------
__global__ void heat_kernel(const float* __restrict__ x)
{
    int bi = blockIdx.x;
    int b = bi >> 5, hu = bi & 31;
    int t = threadIdx.x;
    int g = t >> 6, j = t & 63;
    int r = j >> 5, wu = j & 31;
    const float* xp = x + (size_t)b * NC * NN + (size_t)(2 * hu + r) * 64 + 2 * wu;
    float s = 0.f;
#pragma unroll 4
    for (int c = g * 32; c < g * 32 + 32; c++) {
        float2 v = *(const float2*)(xp + (size_t)c * NN);
        s += v.x + v.y;
    }
    __shared__ float red[1024];
    red[t] = s;
    __syncthreads();
    if (t < 32) {
        float a = 0.f;
#pragma unroll
        for (int gg = 0; gg < 16; gg++)
            a += red[gg * 64 + t] + red[gg * 64 + 32 + t];
        g_heat[b * NUU + hu * 32 + t] = a * (1.f / 2048.f);
    }
}

// ---------------- qmean (1024 threads) ------------------------------------------
__global__ void qmean_kernel()
{
    int bh = blockIdx.x;
    int t = threadIdx.x;
    int d = t & 63, seg = t >> 6;
    float s = 0.f;
    const float* Q = g_q + (size_t)bh * NN * HD;
    for (int n = seg * 256; n < seg * 256 + 256; n++) s += Q[(size_t)n * HD + d];
    __shared__ float red[1024];
    red[t] = s; __syncthreads();
    if (seg == 0) {
        float a = 0.f;
#pragma unroll
        for (int i = 0; i < 16; i++) a += red[i * 64 + d];
        g_qmean[bh * HD + d] = a * (1.f / (float)NN);
    }
}

// ---------------- topk ---------------------------------------------------------
__global__ void topk_kernel(const float* __restrict__ gumbel)
{
    int bh = blockIdx.x;
    int b = bh >> 3;
    int t = threadIdx.x;
    __shared__ float s[NUU];
    __shared__ float qm[HD];
    __shared__ float rv[256];
    __shared__ int   ri[256];
    if (t < HD) qm[t] = g_qmean[bh * HD + t];
    __syncthreads();
    for (int m = t; m < NUU; m += 256) {
        const float* kp = g_k + ((size_t)bh * NUU + m) * HD;
        float dot = 0.f;
#pragma unroll
        for (int d = 0; d < HD; d++) dot += qm[d] * kp[d];
        s[m] = dot * SCALE_ * g_heat[b * NUU + m] + gumbel[(size_t)bh * NUU + m];
    }
    __syncthreads();
    for (int it = 0; it < 16; it++) {
        float bv = -1e30f; int bi = 0x7fffffff;
        for (int m = t; m < NUU; m += 256) {
            float v = s[m];
            if (v > bv || (v == bv && m < bi)) { bv = v; bi = m; }
        }
        rv[t] = bv; ri[t] = bi; __syncthreads();
        for (int off = 128; off; off >>= 1) {
            if (t < off) {
                float v2 = rv[t + off]; int i2 = ri[t + off];
                if (v2 > rv[t] || (v2 == rv[t] && i2 < ri[t])) { rv[t] = v2; ri[t] = i2; }
            }
            __syncthreads();
        }
        if (t == 0) {
            int m = ri[0];
            s[m] = -1e38f;
            int hi = (m >> 5) * 2, wi = (m & 31) * 2;
            int base = hi * 64 + wi;
            g_idxf[bh * 64 +       it] = base;
            g_idxf[bh * 64 + 16 +  it] = base + 1;
            g_idxf[bh * 64 + 32 +  it] = base + 64;
            g_idxf[bh * 64 + 48 +  it] = base + 65;
        }
        __syncthreads();
    }
}

// ---------------- fine attention + gate + blend ----------------------------------
struct FineSmem {
    float Ks[64][65];
    float Vs[64][64];
    float Gw[128][64];
    float Os[64][65];
    int   idx[64];
    float gb[64];
};

__global__ void __launch_bounds__(256, 2)
fine_kernel(const float* __restrict__ gate_w, const float* __restrict__ gate_b)
{
    extern __shared__ char smem_raw[];
    FineSmem* S = reinterpret_cast<FineSmem*>(smem_raw);
    int bh = blockIdx.y;
    int b = bh >> 3, h = bh & 7;
    int ntile = blockIdx.x * 64;
    int t = threadIdx.x;

    if (t < 64) { S->idx[t] = g_idxf[bh * 64 + t]; S->gb[t] = gate_b[t]; }
    for (int e = t; e < 8192; e += 256) {
        int o = e >> 7, c = e & 127;
        S->Gw[c][o] = gate_w[e];
    }
    __syncthreads();
    for (int e = t; e < 4096; e += 256) {
        int m = e >> 6, d = e & 63;
        size_t src = ((size_t)bh * NN + S->idx[m]) * HD + d;
        S->Ks[m][d] = g_fk[src];
        S->Vs[m][d] = g_fv[src];
    }
    __syncthreads();

    int w = t >> 5, l = t & 31;
    for (int qi = 0; qi < 8; qi++) {
        int n = ntile + w * 8 + qi;
        const float* qp = g_q + ((size_t)bh * NN + n) * HD;
        float q0 = qp[l], q1 = qp[l + 32];
        float s0 = 0.f, s1 = 0.f;
#pragma unroll
        for (int d = 0; d < 64; d++) {
            float qd = __shfl_sync(0xffffffffu, d < 32 ? q0 : q1, d & 31);
            s0 += qd * S->Ks[l][d];
            s1 += qd * S->Ks[l + 32][d];
        }
        s0 *= SCALE_; s1 *= SCALE_;
        float mx = fmaxf(s0, s1);
#pragma unroll
        for (int off = 16; off; off >>= 1) mx = fmaxf(mx, __shfl_xor_sync(0xffffffffu, mx, off));
        float p0 = __expf(s0 - mx), p1 = __expf(s1 - mx);
        float sm = p0 + p1;
#pragma unroll
        for (int off = 16; off; off >>= 1) sm += __shfl_xor_sync(0xffffffffu, sm, off);
        float inv = 1.f / sm;
        p0 *= inv; p1 *= inv;

        float r0 = 0.f, r1 = 0.f;
#pragma unroll
        for (int m = 0; m < 64; m++) {
            float pm = __shfl_sync(0xffffffffu, m < 32 ? p0 : p1, m & 31);
            r0 += pm * S->Vs[m][l];
            r1 += pm * S->Vs[m][l + 32];
        }
        const float* cp = g_coarse + ((size_t)bh * NN + n) * HD;
        float c0 = cp[l], c1 = cp[l + 32];

        float g0 = S->gb[l], g1 = S->gb[l + 32];
#pragma unroll
        for (int c = 0; c < 64; c++) {
            float cv = __shfl_sync(0xffffffffu, c < 32 ? c0 : c1, c & 31);
            g0 += cv * S->Gw[c][l];
            g1 += cv * S->Gw[c][l + 32];
        }
#pragma unroll
        for (int c = 0; c < 64; c++) {
            float rvv = __shfl_sync(0xffffffffu, c < 32 ? r0 : r1, c & 31);
            g0 += rvv * S->Gw[64 + c][l];
            g1 += rvv * S->Gw[64 + c][l + 32];
        }
        g0 = 1.f / (1.f + __expf(-g0));
        g1 = 1.f / (1.f + __expf(-g1));
        int nl = w * 8 + qi;
        S->Os[l][nl]      = g0 * r0 + (1.f - g0) * c0;
        S->Os[l + 32][nl] = g1 * r1 + (1.f - g1) * c1;
    }
    __syncthreads();
    for (int e = t; e < 4096; e += 256) {
        int d = e >> 6, nl = e & 63;
        g_xsum[((size_t)b * NC + h * 64 + d) * NN + ntile + nl] = S->Os[d][nl];
    }
}

// ---------------- fused depthwise 7x7 conv + bilinear upsample -> g_pe ---------
__global__ void pe_bilinear(const float* __restrict__ pe_w, const float* __restrict__ pe_b)
{
    int bc = blockIdx.x;
    int b = bc >> 9, c = bc & 511;
    int h = c >> 6, d = c & 63;
    __shared__ float img[1024];
    __shared__ float pet[1024];
    __shared__ float wt[49];
    int t = threadIdx.x;
    for (int p = t; p < 1024; p += 256)
        img[p] = g_v[((size_t)(b * NHEAD + h) * NUU + p) * HD + d];
    if (t < 49) wt[t] = pe_w[c * 49 + t];
    __syncthreads();
    float bias = pe_b[c];
    for (int p = t; p < 1024; p += 256) {
        int y = p >> 5, xx0 = p & 31;
        float s = bias;
#pragma unroll
        for (int ky = 0; ky < 7; ky++) {
            int yy = y + ky - 3;
            if (yy < 0 || yy > 31) continue;
#pragma unroll
            for (int kx = 0; kx < 7; kx++) {
                int xx = xx0 + kx - 3;
                if (xx < 0 || xx > 31) continue;
                s += wt[ky * 7 + kx] * img[yy * 32 + xx];
            }
        }
        pet[p] = s;
    }
    __syncthreads();
    for (int p = t; p < 4096; p += 256) {
        int i = p >> 6, j = p & 63;
        int ti = i >> 1, tj = j >> 1;
        int y0, y1, x0, x1; float wy0, wy1, wx0, wx1;
        if (i & 1) { y0 = ti; y1 = min(ti + 1, 31); wy0 = 0.75f; wy1 = 0.25f; }
        else       { y0 = max(ti - 1, 0); y1 = ti;  wy0 = 0.25f; wy1 = 0.75f; }
        if (j & 1) { x0 = tj; x1 = min(tj + 1, 31); wx0 = 0.75f; wx1 = 0.25f; }
        else       { x0 = max(tj - 1, 0); x1 = tj;  wx0 = 0.25f; wx1 = 0.75f; }
        float v = wy0 * (wx0 * pet[y0 * 32 + x0] + wx1 * pet[y0 * 32 + x1])
                + wy1 * (wx0 * pet[y1 * 32 + x0] + wx1 * pet[y1 * 32 + x1]);
        g_pe[(size_t)bc * 4096 + p] = v;
    }
}

// ---------------- launch: stream-forked DAG --------------------------------------
extern "C" void kernel_launch(void* const* d_in, const int* in_sizes, int n_in,
                              void* d_out, int out_size)
{
    const float* x      = (const float*)d_in[0];
    const float* upper  = (const float*)d_in[1];
    const float* gumbel = (const float*)d_in[2];
    const float* q_w    = (const float*)d_in[3];
    const float* q_b    = (const float*)d_in[4];
    const float* kv_w   = (const float*)d_in[5];
    const float* kv_b   = (const float*)d_in[6];
    const float* proj_w = (const float*)d_in[7];
    const float* proj_b = (const float*)d_in[8];
    const float* pe_w   = (const float*)d_in[9];
    const float* pe_b   = (const float*)d_in[10];
    const float* gate_w = (const float*)d_in[11];
    const float* gate_b = (const float*)d_in[12];
    float* out = (float*)d_out;

    cudaFuncSetAttribute(fine_kernel, cudaFuncAttributeMaxDynamicSharedMemorySize,
                         (int)sizeof(FineSmem));
    cudaFuncSetAttribute(flash_mma, cudaFuncAttributeMaxDynamicSharedMemorySize, FLASH_SMEM);
    cudaFuncSetAttribute(conv_mma<0>, cudaFuncAttributeMaxDynamicSharedMemorySize, CONV_SMEM);
    cudaFuncSetAttribute(conv_mma<1>, cudaFuncAttributeMaxDynamicSharedMemorySize, CONV_SMEM);
    cudaFuncSetAttribute(conv_mma<2>, cudaFuncAttributeMaxDynamicSharedMemorySize, CONV_SMEM);
    cudaFuncSetAttribute(conv_mma<3>, cudaFuncAttributeMaxDynamicSharedMemorySize, CONV_SMEM);

    dim3 blk(256);

    cudaStream_t s1, s2;
    cudaStreamCreateWithFlags(&s1, cudaStreamNonBlocking);
    cudaStreamCreateWithFlags(&s2, cudaStreamNonBlocking);
    cudaEvent_t ev_sw, ev_c0, ev_c3, ev_c1, ev_t;
    cudaEventCreateWithFlags(&ev_sw, cudaEventDisableTiming);
    cudaEventCreateWithFlags(&ev_c0, cudaEventDisableTiming);
    cudaEventCreateWithFlags(&ev_c3, cudaEventDisableTiming);
    cudaEventCreateWithFlags(&ev_c1, cudaEventDisableTiming);
    cudaEventCreateWithFlags(&ev_t,  cudaEventDisableTiming);

    // ---- s2: heat needs only x ----
    heat_kernel<<<NB * 32, 1024, 0, s2>>>(x);

    // ---- main: weights -> conv0 ----
    split_weights<<<2048, blk>>>(q_w, kv_w, proj_w);
    cudaEventRecord(ev_sw, 0);
    conv_mma<0><<<dim3(NN / 128,  512 / 128, NB), blk, CONV_SMEM>>>(x, 0, q_b, nullptr, NN);
    cudaEventRecord(ev_c0, 0);

    // ---- s1: conv3 (concurrent with conv0) -> conv1 ----
    cudaStreamWaitEvent(s1, ev_sw, 0);
    conv_mma<3><<<dim3(NUU / 128, 1024 / 128, NB), blk, CONV_SMEM, s1>>>(upper, 512, kv_b, nullptr, NUU);
    cudaEventRecord(ev_c3, s1);
    conv_mma<1><<<dim3(NN / 128, 1024 / 128, NB), blk, CONV_SMEM, s1>>>(x, 512, kv_b, nullptr, NN);
    cudaEventRecord(ev_c1, s1);

    // ---- s2: qmean (needs conv0) -> topk (needs conv3) -> pe (needs conv3) ----
    cudaStreamWaitEvent(s2, ev_c0, 0);
    qmean_kernel<<<NB * NHEAD, 1024, 0, s2>>>();
    cudaStreamWaitEvent(s2, ev_c3, 0);
    topk_kernel<<<NB * NHEAD, blk, 0, s2>>>(gumbel);
    pe_bilinear<<<NB * NC, blk, 0, s2>>>(pe_w, pe_b);
    cudaEventRecord(ev_t, s2);

    // ---- main: flash (needs conv0 + conv3), concurrent with s1/s2 ----
    cudaStreamWaitEvent(0, ev_c3, 0);
    flash_mma<<<dim3(NN / 128, NB * NHEAD), blk, FLASH_SMEM>>>();

    // ---- join, then tail ----
    cudaStreamWaitEvent(0, ev_c1, 0);
    cudaStreamWaitEvent(0, ev_t, 0);

    fine_kernel<<<dim3(NN / 64, NB * NHEAD), blk, sizeof(FineSmem)>>>(gate_w, gate_b);
    conv_mma<2><<<dim3(NN / 128, 512 / 128, NB), blk, CONV_SMEM>>>(nullptr, 1536, proj_b, out, NN);

    cudaEventDestroy(ev_sw);
    cudaEventDestroy(ev_c0);
    cudaEventDestroy(ev_c3);
    cudaEventDestroy(ev_c1);
    cudaEventDestroy(ev_t);
    cudaStreamDestroy(s1);
    cudaStreamDestroy(s2);
}